// round 12
// baseline (speedup 1.0000x reference)
#include <cuda_runtime.h>
#include <cuda_fp16.h>
#include <math.h>

#define NB   4
#define NN   15135
#define FIN0 8
#define HH   64
#define NE   302700
#define ETOT (NE + NN)
#define FCN  256
#define NL   3
#define RT   74
#define RPB  205                   // 74*205 = 15170 >= NN
#define NROWS (NB * NN)            // 60540
#define NROWS_PAD (NROWS + 16)
#define CSRB 256                   // blocks in the fused CSR kernel
#define CPB  60                    // nodes per CSR block
#define MB   592                   // mega kernel blocks = 4/SM * 148
#define MW   (MB * 8)              // mega warps
#define GTILES ((NROWS + 15) / 16) // 3784 gemm tiles
#define LOG2E 1.4426950408889634f

// ---------------------------------------------------------------------------
// Static device scratch.  h layout: [node][batch][ch] half (512 B / node).
// es/ed are PRE-SCALED by log2(e) so the edge loop uses ex2 directly.
// ---------------------------------------------------------------------------
__device__ __half g_hA16[(size_t)NROWS_PAD * HH];
__device__ __half g_hB16[(size_t)NROWS_PAD * HH];
__device__ __half g_Wt[2][HH * HH];
__device__ float g_es4[NL][NN * NB];
__device__ float g_ed4[NL][NN * NB];
__device__ float g_scores[NB * NN];
__device__ float g_h1part[RT * NB * FCN];
__device__ float g_wa[NL][2][HH];          // pre-scaled by LOG2E
__device__ int   g_cnt[NN];
__device__ int   g_rowptr[NN + 1];
__device__ int   g_wp[NN];
__device__ int   g_srcs[ETOT];
__device__ unsigned g_bar;                 // csr barrier counter (group 256)
__device__ unsigned g_bar2;                // mega barrier counter (group 592)
__device__ int   g_part[CSRB];
__device__ int   g_ppre[CSRB];

__device__ __forceinline__ __half* selbuf16(int s) { return s ? g_hB16 : g_hA16; }

__device__ __forceinline__ float ex2f(float x) {
    float r;
    asm("ex2.approx.ftz.f32 %0, %1;" : "=f"(r) : "f"(x));
    return r;
}

// Monotonic grid barriers (never reset; per-exec arrivals are multiples of
// the group size, so targets stay aligned across correctness run + replays).
__device__ __forceinline__ void gridbar256() {
    __syncthreads();
    if (threadIdx.x == 0) {
        __threadfence();
        unsigned old = atomicAdd(&g_bar, 1u);
        unsigned target = old - (old & (CSRB - 1)) + CSRB;
        volatile unsigned* p = &g_bar;
        while (*p < target) { }
        __threadfence();
    }
    __syncthreads();
}

__device__ __forceinline__ void megabar() {
    __syncthreads();
    if (threadIdx.x == 0) {
        __threadfence();
        unsigned old = atomicAdd(&g_bar2, 1u);
        unsigned target = old - (old % MB) + MB;
        volatile unsigned* p = &g_bar2;
        while (*p < target) { }
        __threadfence();
    }
    __syncthreads();
}

// ---------------------------------------------------------------------------
// Fused CSR build: histogram -> scan -> scatter (validated in prior rounds).
// ---------------------------------------------------------------------------
__global__ void __launch_bounds__(256) k_csr(const int* __restrict__ src,
                                             const int* __restrict__ dst) {
    int tid = threadIdx.x, bid = blockIdx.x;
    int gt = bid * 256 + tid;

    for (int i = gt; i < NE; i += CSRB * 256)
        atomicAdd(&g_cnt[dst[i]], 1);
    gridbar256();

    __shared__ int ss[64];
    int n0 = bid * CPB;
    int v = 0;
    if (tid < CPB) {
        int n = n0 + tid;
        if (n < NN) { v = g_cnt[n] + 1; g_cnt[n] = 0; }
    }
    if (tid < 64) ss[tid] = (tid < CPB) ? v : 0;
    __syncthreads();
    for (int off = 1; off < 64; off <<= 1) {
        int add = 0;
        if (tid < 64 && tid >= off) add = ss[tid - off];
        __syncthreads();
        if (tid < 64) ss[tid] += add;
        __syncthreads();
    }
    if (tid == 0) g_part[bid] = ss[63];
    gridbar256();

    if (bid == 0) {
        __shared__ int sp[CSRB];
        int pv = g_part[tid];
        sp[tid] = pv;
        __syncthreads();
        for (int off = 1; off < CSRB; off <<= 1) {
            int add = (tid >= off) ? sp[tid - off] : 0;
            __syncthreads();
            sp[tid] += add;
            __syncthreads();
        }
        g_ppre[tid] = sp[tid] - pv;
        if (tid == CSRB - 1) g_rowptr[NN] = sp[CSRB - 1];
    }
    gridbar256();

    int base = g_ppre[bid];
    if (tid < CPB) {
        int n = n0 + tid;
        if (n < NN) {
            int r = base + ss[tid] - v;
            g_rowptr[n] = r;
            g_wp[n] = r;
        }
    }
    gridbar256();

    for (int i = gt; i < ETOT; i += CSRB * 256) {
        int s, d;
        if (i < NE) { s = src[i]; d = dst[i]; }
        else        { s = d = i - NE; }
        int pos = atomicAdd(&g_wp[d], 1);
        g_srcs[pos] = s;
    }
}

// ---------------------------------------------------------------------------
// Misc prologue: wa (scaled by LOG2E) + fp16 W^T. 1 block.
// ---------------------------------------------------------------------------
__global__ void k_misc(const float* __restrict__ W1, const float* __restrict__ as1, const float* __restrict__ ad1,
                       const float* __restrict__ W2, const float* __restrict__ as2, const float* __restrict__ ad2) {
    int tid = threadIdx.x;
    if (tid < HH) {
        int f = tid;
        float s1 = 0.f, d1 = 0.f, s2 = 0.f, d2 = 0.f;
        for (int h = 0; h < HH; h++) {
            s1 += W1[f * HH + h] * as1[h]; d1 += W1[f * HH + h] * ad1[h];
            s2 += W2[f * HH + h] * as2[h]; d2 += W2[f * HH + h] * ad2[h];
        }
        g_wa[1][0][f] = s1 * LOG2E; g_wa[1][1][f] = d1 * LOG2E;
        g_wa[2][0][f] = s2 * LOG2E; g_wa[2][1][f] = d2 * LOG2E;
    }
    for (int e = tid; e < HH * HH; e += 256) {
        int c = e / HH, f = e % HH;
        g_Wt[0][e] = __float2half(W1[f * HH + c]);
        g_Wt[1][e] = __float2half(W2[f * HH + c]);
    }
}

// ---------------------------------------------------------------------------
// Layer 0: h0 = x @ W0 (fp16), es0/ed0 (pre-scaled by LOG2E).
// ---------------------------------------------------------------------------
__global__ void k_lin0(const float* __restrict__ x, const float* __restrict__ W,
                       const float* __restrict__ as0, const float* __restrict__ ad0) {
    __shared__ float sW[FIN0 * HH];
    __shared__ float sx[16][FIN0];
    __shared__ float swa[2][FIN0];

    int tid = threadIdx.x;
    for (int i = tid; i < FIN0 * HH; i += 256) sW[i] = W[i];

    int bn0 = blockIdx.x * 16;
    for (int i = tid; i < 16 * FIN0; i += 256) {
        int bn = bn0 + i / FIN0;
        sx[i / FIN0][i % FIN0] = (bn < NROWS) ? x[(size_t)bn * FIN0 + (i % FIN0)] : 0.f;
    }
    __syncthreads();

    if (tid < 2 * FIN0) {
        int sel = tid >> 3, f = tid & 7;
        const float* a = sel ? ad0 : as0;
        float s = 0.f;
#pragma unroll
        for (int h = 0; h < HH; h++) s += sW[f * HH + h] * a[h];
        swa[sel][f] = s * LOG2E;
    }
    __syncthreads();

    int g = tid >> 6, c = tid & 63;
#pragma unroll
    for (int jj = 0; jj < 4; jj++) {
        int gg = g + jj * 4;
        int bn = bn0 + gg;
        float acc = 0.f;
#pragma unroll
        for (int f = 0; f < FIN0; f++) acc += sx[gg][f] * sW[f * HH + c];
        if (bn < NROWS) {
            int b = bn / NN, node = bn - b * NN;
            g_hA16[((size_t)node * NB + b) * HH + c] = __float2half(acc);
        }
    }

    if (tid < 32) {
        int j = tid >> 1, sel = tid & 1;
        int bn = bn0 + j;
        if (bn < NROWS) {
            float s = 0.f;
#pragma unroll
            for (int f = 0; f < FIN0; f++) s += sx[j][f] * swa[sel][f];
            int b = bn / NN, node = bn - b * NN;
            if (sel == 0) g_es4[0][node * NB + b] = s;
            else          g_ed4[0][node * NB + b] = s;
        }
    }
}

// ---------------------------------------------------------------------------
// MEGA kernel phases (persistent, 592 blocks, grid barriers between phases).
// Cross-phase data uses PLAIN loads (barrier's __threadfence flushes L1D).
// ---------------------------------------------------------------------------
template <bool LAST>
__device__ __forceinline__ void agg_phase(int insel, int layer,
                                          const float* __restrict__ bvec,
                                          const float* __restrict__ fcw) {
    int gw = (blockIdx.x * 256 + threadIdx.x) >> 5;
    int lane = threadIdx.x & 31;
    int myb = lane >> 3;
    int mych = (lane & 7) * 8;

    const float* esl = g_es4[layer];
    const uint4* hb = (const uint4*)selbuf16(insel);

    float4 bb0 = __ldg((const float4*)(bvec + mych));
    float4 bb1 = __ldg((const float4*)(bvec + mych + 4));
    float fw[8];
#pragma unroll
    for (int k = 0; k < 8; k++) fw[k] = __ldg(&fcw[(mych + k) * NL + layer]);

    for (int node = gw; node < NN; node += MW) {
        int beg = g_rowptr[node], end = g_rowptr[node + 1];
        float edv = g_ed4[layer][node * NB + myb];

        float acc[8];
#pragma unroll
        for (int k = 0; k < 8; k++) acc[k] = 0.f;
        float den = 0.f;

#pragma unroll 4
        for (int i = beg; i < end; i++) {
            int s = __ldg(&g_srcs[i]);
            float v = esl[s * NB + myb] + edv;       // pre-scaled by log2(e)
            v = fmaxf(v, 0.2f * v);                  // leaky (homogeneous)
            float ex = ex2f(v);
            den += ex;
            uint4 hv = hb[(size_t)s * 32 + lane];
            float2 p0 = __half22float2(*(__half2*)&hv.x);
            float2 p1 = __half22float2(*(__half2*)&hv.y);
            float2 p2 = __half22float2(*(__half2*)&hv.z);
            float2 p3 = __half22float2(*(__half2*)&hv.w);
            acc[0] += ex * p0.x; acc[1] += ex * p0.y;
            acc[2] += ex * p1.x; acc[3] += ex * p1.y;
            acc[4] += ex * p2.x; acc[5] += ex * p2.y;
            acc[6] += ex * p3.x; acc[7] += ex * p3.y;
        }

        float inv = 1.f / den;
        float o[8];
        o[0] = acc[0] * inv + bb0.x; o[1] = acc[1] * inv + bb0.y;
        o[2] = acc[2] * inv + bb0.z; o[3] = acc[3] * inv + bb0.w;
        o[4] = acc[4] * inv + bb1.x; o[5] = acc[5] * inv + bb1.y;
        o[6] = acc[6] * inv + bb1.z; o[7] = acc[7] * inv + bb1.w;
#pragma unroll
        for (int k = 0; k < 8; k++) o[k] = (o[k] > 0.f) ? o[k] : 0.f;

        {
            float sc = 0.f;
#pragma unroll
            for (int k = 0; k < 8; k++) sc += o[k] * fw[k];
#pragma unroll
            for (int off = 4; off; off >>= 1)
                sc += __shfl_xor_sync(0xffffffffu, sc, off);
            if ((lane & 7) == 0) {
                if (layer == 0) g_scores[myb * NN + node] = sc;
                else            g_scores[myb * NN + node] += sc;
            }
        }

        if (!LAST) {
            int nl = layer + 1;
            float se = 0.f, sd = 0.f;
#pragma unroll
            for (int k = 0; k < 8; k++) {
                se += o[k] * g_wa[nl][0][mych + k];
                sd += o[k] * g_wa[nl][1][mych + k];
            }
#pragma unroll
            for (int off = 4; off; off >>= 1) {
                se += __shfl_xor_sync(0xffffffffu, se, off);
                sd += __shfl_xor_sync(0xffffffffu, sd, off);
            }
            if ((lane & 7) == 0) {
                g_es4[nl][node * NB + myb] = se;
                g_ed4[nl][node * NB + myb] = sd;
            }
            uint4 ov;
            ((__half2*)&ov)[0] = __floats2half2_rn(o[0], o[1]);
            ((__half2*)&ov)[1] = __floats2half2_rn(o[2], o[3]);
            ((__half2*)&ov)[2] = __floats2half2_rn(o[4], o[5]);
            ((__half2*)&ov)[3] = __floats2half2_rn(o[6], o[7]);
            ((uint4*)selbuf16(insel ^ 1))[((size_t)node * NB + myb) * 8 + (lane & 7)] = ov;
        }
    }
}

__device__ __forceinline__ void gemm_phase(int isel, int osel, int wsel) {
    const __half* O  = selbuf16(isel);
    __half* Hn = selbuf16(osel);
    const __half* Wt = g_Wt[wsel];
    int gw = (blockIdx.x * 256 + threadIdx.x) >> 5;
    int lane = threadIdx.x & 31;
    int t = lane & 3, g = lane >> 2;

    for (int tile = gw; tile < GTILES; tile += MW) {
        int rbase = tile * 16;
        int row0 = rbase + g, row1 = row0 + 8;

        unsigned a[4][4];
#pragma unroll
        for (int kc = 0; kc < 4; kc++) {
            int k0 = kc * 16 + 2 * t;
            a[kc][0] = *(const unsigned*)&O[(size_t)row0 * HH + k0];
            a[kc][1] = *(const unsigned*)&O[(size_t)row1 * HH + k0];
            a[kc][2] = *(const unsigned*)&O[(size_t)row0 * HH + k0 + 8];
            a[kc][3] = *(const unsigned*)&O[(size_t)row1 * HH + k0 + 8];
        }
#pragma unroll
        for (int nt = 0; nt < 8; nt++) {
            int n = nt * 8 + g;
            float c0 = 0.f, c1 = 0.f, c2 = 0.f, c3 = 0.f;
#pragma unroll
            for (int kc = 0; kc < 4; kc++) {
                int k0 = kc * 16 + 2 * t;
                unsigned b0 = *(const unsigned*)&g_Wt[wsel][n * HH + k0];
                unsigned b1 = *(const unsigned*)&g_Wt[wsel][n * HH + k0 + 8];
                asm volatile(
                    "mma.sync.aligned.m16n8k16.row.col.f32.f16.f16.f32 "
                    "{%0,%1,%2,%3}, {%4,%5,%6,%7}, {%8,%9}, {%0,%1,%2,%3};\n"
                    : "+f"(c0), "+f"(c1), "+f"(c2), "+f"(c3)
                    : "r"(a[kc][0]), "r"(a[kc][1]), "r"(a[kc][2]), "r"(a[kc][3]),
                      "r"(b0), "r"(b1));
            }
            int col = nt * 8 + 2 * t;
            if (row0 < NROWS) *(__half2*)&Hn[(size_t)row0 * HH + col] = __floats2half2_rn(c0, c1);
            if (row1 < NROWS) *(__half2*)&Hn[(size_t)row1 * HH + col] = __floats2half2_rn(c2, c3);
        }
    }
    (void)Wt;
}

__global__ void __launch_bounds__(256, 4) k_mega(
    const float* __restrict__ b0v, const float* __restrict__ b1v, const float* __restrict__ b2v,
    const float* __restrict__ fcw, const float* __restrict__ fcb,
    const float* __restrict__ w1, const float* __restrict__ l1b,
    const float* __restrict__ w2, const float* __restrict__ l2b,
    float* __restrict__ out) {

    __shared__ float sh[8][32][16];      // final phase
    __shared__ float h1s[NB][FCN];       // head phase
    __shared__ float lg[NB][2];

    agg_phase<false>(0, 0, b0v, fcw);  megabar();
    gemm_phase(1, 0, 0);               megabar();
    agg_phase<false>(0, 1, b1v, fcw);  megabar();
    gemm_phase(1, 0, 1);               megabar();
    agg_phase<true >(0, 2, b2v, fcw);  megabar();

    // ---- final: partial (scores+fcb) @ w1, blocks 0..147 ----
    if (blockIdx.x < 2 * RT) {
        int tid = threadIdx.x;
        int lane = tid & 31, ty = tid >> 5;
        int cbt = blockIdx.x & 1, rt = blockIdx.x >> 1;
        int cb = cbt * 128 + lane * 4;
        int n0 = rt * RPB;
        int n1 = min(NN, n0 + RPB);
        float f0 = __ldg(fcb);

        float acc[NB][4];
#pragma unroll
        for (int b = 0; b < NB; b++)
#pragma unroll
            for (int j = 0; j < 4; j++) acc[b][j] = 0.f;

        for (int n = n0 + ty; n < n1; n += 8) {
            float4 w = __ldg((const float4*)&w1[(size_t)n * FCN + cb]);
            float sc[NB];
#pragma unroll
            for (int b = 0; b < NB; b++) sc[b] = g_scores[b * NN + n] + f0;
#pragma unroll
            for (int b = 0; b < NB; b++) {
                acc[b][0] += sc[b] * w.x;
                acc[b][1] += sc[b] * w.y;
                acc[b][2] += sc[b] * w.z;
                acc[b][3] += sc[b] * w.w;
            }
        }
#pragma unroll
        for (int b = 0; b < NB; b++)
#pragma unroll
            for (int j = 0; j < 4; j++) sh[ty][lane][b * 4 + j] = acc[b][j];
        __syncthreads();

        int t = ty * 32 + lane;
#pragma unroll
        for (int q = t; q < 512; q += 256) {
            int ln = q >> 4, idx = q & 15;
            int b = idx >> 2, j = idx & 3;
            float s = 0.f;
#pragma unroll
            for (int k = 0; k < 8; k++) s += sh[k][ln][idx];
            g_h1part[(size_t)rt * NB * FCN + b * FCN + cbt * 128 + ln * 4 + j] = s;
        }
    }
    megabar();

    // ---- head: reduce partials, relu, lin2, log_softmax (block 0) ----
    if (blockIdx.x == 0) {
        int tid = threadIdx.x;
        {
            int c = tid;
            float s[NB] = {0.f, 0.f, 0.f, 0.f};
            for (int rt = 0; rt < RT; rt++) {
                const float* p = g_h1part + (size_t)rt * NB * FCN;
#pragma unroll
                for (int b = 0; b < NB; b++) s[b] += p[b * FCN + c];
            }
            float bb = __ldg(&l1b[c]);
#pragma unroll
            for (int b = 0; b < NB; b++) {
                float v = s[b] + bb;
                h1s[b][c] = (v > 0.f) ? v : 0.f;
            }
        }
        __syncthreads();

        int w = tid >> 5, lane = tid & 31;
        if (w < NB * 2) {
            int b = w >> 1, cls = w & 1;
            float acc = 0.f;
            for (int j = lane; j < FCN; j += 32)
                acc += h1s[b][j] * __ldg(&w2[j * 2 + cls]);
            for (int off = 16; off; off >>= 1)
                acc += __shfl_xor_sync(0xffffffffu, acc, off);
            if (lane == 0) lg[b][cls] = acc + __ldg(&l2b[cls]);
        }
        __syncthreads();
        if (tid < NB) {
            float l0 = lg[tid][0], l1 = lg[tid][1];
            float mm = fmaxf(l0, l1);
            float lse = mm + logf(__expf(l0 - mm) + __expf(l1 - mm));
            out[tid * 2 + 0] = l0 - lse;
            out[tid * 2 + 1] = l1 - lse;
        }
    }
}

// ---------------------------------------------------------------------------
// Launch: 4 kernels total; #4 (mega) sits in the ncu capture slot.
// ---------------------------------------------------------------------------
extern "C" void kernel_launch(void* const* d_in, const int* in_sizes, int n_in,
                              void* d_out, int out_size) {
    const float* x   = (const float*)d_in[0];
    const int*   ei  = (const int*)d_in[1];
    const float* W0  = (const float*)d_in[3];
    const float* as0 = (const float*)d_in[4];
    const float* ad0 = (const float*)d_in[5];
    const float* b0  = (const float*)d_in[6];
    const float* W1  = (const float*)d_in[7];
    const float* as1 = (const float*)d_in[8];
    const float* ad1 = (const float*)d_in[9];
    const float* b1  = (const float*)d_in[10];
    const float* W2  = (const float*)d_in[11];
    const float* as2 = (const float*)d_in[12];
    const float* ad2 = (const float*)d_in[13];
    const float* b2  = (const float*)d_in[14];
    const float* fcw = (const float*)d_in[15];
    const float* fcb = (const float*)d_in[16];
    const float* l1w = (const float*)d_in[17];
    const float* l1b = (const float*)d_in[18];
    const float* l2w = (const float*)d_in[19];
    const float* l2b = (const float*)d_in[20];
    float* out = (float*)d_out;

    const int* srcp = ei;
    const int* dstp = ei + NE;

    k_lin0<<<(NROWS + 15) / 16, 256>>>(x, W0, as0, ad0);            // 1
    k_csr<<<CSRB, 256>>>(srcp, dstp);                               // 2
    k_misc<<<1, 256>>>(W1, as1, ad1, W2, as2, ad2);                 // 3
    k_mega<<<MB, 256>>>(b0, b1, b2, fcw, fcb, l1w, l1b, l2w, l2b, out); // 4
}

// round 13
// speedup vs baseline: 1.0831x; 1.0831x over previous
#include <cuda_runtime.h>
#include <cuda_fp16.h>
#include <math.h>

#define NB   4
#define NN   15135
#define FIN0 8
#define HH   64
#define NE   302700
#define ETOT (NE + NN)
#define FCN  256
#define NL   3
#define RT   74
#define RPB  205                   // 74*205 = 15170 >= NN
#define NROWS (NB * NN)            // 60540
#define NROWS_PAD (NROWS + 16)
#define CSRB 256
#define CPB  60
#define LOG2E 1.4426950408889634f

// ---------------------------------------------------------------------------
// Static device scratch.  h layout: [node][batch][ch] half (512 B / node).
// es/ed are PRE-SCALED by log2(e) so the edge loop uses ex2 directly.
// ---------------------------------------------------------------------------
__device__ __half g_hA16[(size_t)NROWS_PAD * HH];
__device__ __half g_hB16[(size_t)NROWS_PAD * HH];
__device__ __half g_Wt[2][HH * HH];        // W1^T, W2^T fp16 ([c][f])
__device__ float g_es4[NL][NN * NB];
__device__ float g_ed4[NL][NN * NB];
__device__ float g_scores[NB * NN];
__device__ float g_h1part[RT * NB * FCN];
__device__ float g_wa[NL][2][HH];          // pre-scaled by LOG2E
__device__ int   g_cnt[NN];                // zero-init; reset each exec
__device__ int   g_rowptr[NN + 1];
__device__ int   g_wp[NN];
__device__ int   g_srcs[ETOT];
__device__ unsigned g_bar;                 // monotonic grid-barrier counter
__device__ int   g_part[CSRB];
__device__ int   g_ppre[CSRB];

__device__ __forceinline__ __half* selbuf16(int s) { return s ? g_hB16 : g_hA16; }

__device__ __forceinline__ float ex2f(float x) {
    float r;
    asm("ex2.approx.ftz.f32 %0, %1;" : "=f"(r) : "f"(x));
    return r;
}

// Monotonic grid barrier (never reset; per-exec arrivals are multiples of
// CSRB, so targets stay aligned across correctness run + graph replays).
__device__ __forceinline__ void gridbar256() {
    __syncthreads();
    if (threadIdx.x == 0) {
        __threadfence();
        unsigned old = atomicAdd(&g_bar, 1u);
        unsigned target = old - (old & (CSRB - 1)) + CSRB;
        volatile unsigned* p = &g_bar;
        while (*p < target) { }
        __threadfence();
    }
    __syncthreads();
}

// ---------------------------------------------------------------------------
// Fused CSR build: histogram -> scan -> scatter (validated r11).
// ---------------------------------------------------------------------------
__global__ void __launch_bounds__(256) k_csr(const int* __restrict__ src,
                                             const int* __restrict__ dst) {
    int tid = threadIdx.x, bid = blockIdx.x;
    int gt = bid * 256 + tid;

    for (int i = gt; i < NE; i += CSRB * 256)
        atomicAdd(&g_cnt[dst[i]], 1);
    gridbar256();

    __shared__ int ss[64];
    int n0 = bid * CPB;
    int v = 0;
    if (tid < CPB) {
        int n = n0 + tid;
        if (n < NN) { v = g_cnt[n] + 1; g_cnt[n] = 0; }
    }
    if (tid < 64) ss[tid] = (tid < CPB) ? v : 0;
    __syncthreads();
    for (int off = 1; off < 64; off <<= 1) {
        int add = 0;
        if (tid < 64 && tid >= off) add = ss[tid - off];
        __syncthreads();
        if (tid < 64) ss[tid] += add;
        __syncthreads();
    }
    if (tid == 0) g_part[bid] = ss[63];
    gridbar256();

    if (bid == 0) {
        __shared__ int sp[CSRB];
        int pv = g_part[tid];
        sp[tid] = pv;
        __syncthreads();
        for (int off = 1; off < CSRB; off <<= 1) {
            int add = (tid >= off) ? sp[tid - off] : 0;
            __syncthreads();
            sp[tid] += add;
            __syncthreads();
        }
        g_ppre[tid] = sp[tid] - pv;
        if (tid == CSRB - 1) g_rowptr[NN] = sp[CSRB - 1];
    }
    gridbar256();

    int base = g_ppre[bid];
    if (tid < CPB) {
        int n = n0 + tid;
        if (n < NN) {
            int r = base + ss[tid] - v;
            g_rowptr[n] = r;
            g_wp[n] = r;
        }
    }
    gridbar256();

    for (int i = gt; i < ETOT; i += CSRB * 256) {
        int s, d;
        if (i < NE) { s = src[i]; d = dst[i]; }
        else        { s = d = i - NE; }
        int pos = atomicAdd(&g_wp[d], 1);
        g_srcs[pos] = s;
    }
}

// ---------------------------------------------------------------------------
// Misc prologue: wa (scaled by LOG2E) + fp16 W^T. 1 block.
// ---------------------------------------------------------------------------
__global__ void k_misc(const float* __restrict__ W1, const float* __restrict__ as1, const float* __restrict__ ad1,
                       const float* __restrict__ W2, const float* __restrict__ as2, const float* __restrict__ ad2) {
    int tid = threadIdx.x;
    if (tid < HH) {
        int f = tid;
        float s1 = 0.f, d1 = 0.f, s2 = 0.f, d2 = 0.f;
        for (int h = 0; h < HH; h++) {
            s1 += W1[f * HH + h] * as1[h]; d1 += W1[f * HH + h] * ad1[h];
            s2 += W2[f * HH + h] * as2[h]; d2 += W2[f * HH + h] * ad2[h];
        }
        g_wa[1][0][f] = s1 * LOG2E; g_wa[1][1][f] = d1 * LOG2E;
        g_wa[2][0][f] = s2 * LOG2E; g_wa[2][1][f] = d2 * LOG2E;
    }
    for (int e = tid; e < HH * HH; e += 256) {
        int c = e / HH, f = e % HH;           // Wt[c][f] = W[f][c]
        g_Wt[0][e] = __float2half(W1[f * HH + c]);
        g_Wt[1][e] = __float2half(W2[f * HH + c]);
    }
}

// ---------------------------------------------------------------------------
// Layer 0: h0 = x @ W0 (fp16), es0/ed0 (pre-scaled by LOG2E).
// ---------------------------------------------------------------------------
__global__ void k_lin0(const float* __restrict__ x, const float* __restrict__ W,
                       const float* __restrict__ as0, const float* __restrict__ ad0) {
    __shared__ float sW[FIN0 * HH];
    __shared__ float sx[16][FIN0];
    __shared__ float swa[2][FIN0];

    int tid = threadIdx.x;
    for (int i = tid; i < FIN0 * HH; i += 256) sW[i] = W[i];

    int bn0 = blockIdx.x * 16;
    for (int i = tid; i < 16 * FIN0; i += 256) {
        int bn = bn0 + i / FIN0;
        sx[i / FIN0][i % FIN0] = (bn < NROWS) ? x[(size_t)bn * FIN0 + (i % FIN0)] : 0.f;
    }
    __syncthreads();

    if (tid < 2 * FIN0) {
        int sel = tid >> 3, f = tid & 7;
        const float* a = sel ? ad0 : as0;
        float s = 0.f;
#pragma unroll
        for (int h = 0; h < HH; h++) s += sW[f * HH + h] * a[h];
        swa[sel][f] = s * LOG2E;
    }
    __syncthreads();

    int g = tid >> 6, c = tid & 63;
#pragma unroll
    for (int jj = 0; jj < 4; jj++) {
        int gg = g + jj * 4;
        int bn = bn0 + gg;
        float acc = 0.f;
#pragma unroll
        for (int f = 0; f < FIN0; f++) acc += sx[gg][f] * sW[f * HH + c];
        if (bn < NROWS) {
            int b = bn / NN, node = bn - b * NN;
            g_hA16[((size_t)node * NB + b) * HH + c] = __float2half(acc);
        }
    }

    if (tid < 32) {
        int j = tid >> 1, sel = tid & 1;
        int bn = bn0 + j;
        if (bn < NROWS) {
            float s = 0.f;
#pragma unroll
            for (int f = 0; f < FIN0; f++) s += sx[j][f] * swa[sel][f];
            int b = bn / NN, node = bn - b * NN;
            if (sel == 0) g_es4[0][node * NB + b] = s;
            else          g_ed4[0][node * NB + b] = s;
        }
    }
}

// ---------------------------------------------------------------------------
// Aggregation (r11 structure). One warp per node; lane = (batch, 8 channels).
// Logits pre-scaled by log2(e): exp(leaky(v)) == exp2(leaky(v')), leaky via
// fmaxf (positively homogeneous), ex2.approx directly.
// ---------------------------------------------------------------------------
template <bool LAST>
__global__ void k_agg(int insel, int layer,
                      const float* __restrict__ bvec,
                      const float* __restrict__ fcw) {
    int tid = threadIdx.x;
    int node = (blockIdx.x * blockDim.x + tid) >> 5;
    int lane = tid & 31;
    if (node >= NN) return;

    int myb = lane >> 3;
    int mych = (lane & 7) * 8;

    const float* esl = g_es4[layer];
    int beg = g_rowptr[node], end = g_rowptr[node + 1];
    float edv = g_ed4[layer][node * NB + myb];

    const uint4* hb = (const uint4*)selbuf16(insel);
    float acc[8];
#pragma unroll
    for (int k = 0; k < 8; k++) acc[k] = 0.f;
    float den = 0.f;

#pragma unroll 4
    for (int i = beg; i < end; i++) {
        int s = __ldg(&g_srcs[i]);
        float v = __ldg(&esl[s * NB + myb]) + edv;   // pre-scaled by log2(e)
        v = fmaxf(v, 0.2f * v);                      // leaky (homogeneous)
        float ex = ex2f(v);
        den += ex;
        uint4 hv = __ldg(&hb[(size_t)s * 32 + lane]);
        float2 p0 = __half22float2(*(__half2*)&hv.x);
        float2 p1 = __half22float2(*(__half2*)&hv.y);
        float2 p2 = __half22float2(*(__half2*)&hv.z);
        float2 p3 = __half22float2(*(__half2*)&hv.w);
        acc[0] += ex * p0.x; acc[1] += ex * p0.y;
        acc[2] += ex * p1.x; acc[3] += ex * p1.y;
        acc[4] += ex * p2.x; acc[5] += ex * p2.y;
        acc[6] += ex * p3.x; acc[7] += ex * p3.y;
    }

    float inv = 1.f / den;
    float4 bb0 = __ldg((const float4*)(bvec + mych));
    float4 bb1 = __ldg((const float4*)(bvec + mych + 4));
    float o[8];
    o[0] = acc[0] * inv + bb0.x; o[1] = acc[1] * inv + bb0.y;
    o[2] = acc[2] * inv + bb0.z; o[3] = acc[3] * inv + bb0.w;
    o[4] = acc[4] * inv + bb1.x; o[5] = acc[5] * inv + bb1.y;
    o[6] = acc[6] * inv + bb1.z; o[7] = acc[7] * inv + bb1.w;
#pragma unroll
    for (int k = 0; k < 8; k++) o[k] = (o[k] > 0.f) ? o[k] : 0.f;

    // score contribution: feature index = ch*NL + layer
    {
        float sc = 0.f;
#pragma unroll
        for (int k = 0; k < 8; k++) sc += o[k] * __ldg(&fcw[(mych + k) * NL + layer]);
#pragma unroll
        for (int off = 4; off; off >>= 1)
            sc += __shfl_xor_sync(0xffffffffu, sc, off);
        if ((lane & 7) == 0) {
            if (layer == 0) g_scores[myb * NN + node] = sc;
            else            g_scores[myb * NN + node] += sc;
        }
    }

    if (!LAST) {
        int nl = layer + 1;
        float se = 0.f, sd = 0.f;
#pragma unroll
        for (int k = 0; k < 8; k++) {
            se += o[k] * g_wa[nl][0][mych + k];
            sd += o[k] * g_wa[nl][1][mych + k];
        }
#pragma unroll
        for (int off = 4; off; off >>= 1) {
            se += __shfl_xor_sync(0xffffffffu, se, off);
            sd += __shfl_xor_sync(0xffffffffu, sd, off);
        }
        if ((lane & 7) == 0) {
            g_es4[nl][node * NB + myb] = se;
            g_ed4[nl][node * NB + myb] = sd;
        }
        uint4 ov;
        ((__half2*)&ov)[0] = __floats2half2_rn(o[0], o[1]);
        ((__half2*)&ov)[1] = __floats2half2_rn(o[2], o[3]);
        ((__half2*)&ov)[2] = __floats2half2_rn(o[4], o[5]);
        ((__half2*)&ov)[3] = __floats2half2_rn(o[6], o[7]);
        ((uint4*)selbuf16(insel ^ 1))[((size_t)node * NB + myb) * 8 + (lane & 7)] = ov;
    }
}

// ---------------------------------------------------------------------------
// H_next = O @ W via mma.sync m16n8k16 (fp16 in, fp32 acc).
// ---------------------------------------------------------------------------
__global__ void __launch_bounds__(128, 1) k_gemm(int isel, int osel, int wsel) {
    const __half* O  = selbuf16(isel);
    __half* Hn = selbuf16(osel);
    const __half* Wt = g_Wt[wsel];
    int warp = (blockIdx.x * blockDim.x + threadIdx.x) >> 5;
    int lane = threadIdx.x & 31;
    int rbase = warp * 16;
    if (rbase >= NROWS) return;
    int t = lane & 3, g = lane >> 2;
    int row0 = rbase + g, row1 = row0 + 8;

    unsigned a[4][4];
#pragma unroll
    for (int kc = 0; kc < 4; kc++) {
        int k0 = kc * 16 + 2 * t;
        a[kc][0] = *(const unsigned*)&O[(size_t)row0 * HH + k0];
        a[kc][1] = *(const unsigned*)&O[(size_t)row1 * HH + k0];
        a[kc][2] = *(const unsigned*)&O[(size_t)row0 * HH + k0 + 8];
        a[kc][3] = *(const unsigned*)&O[(size_t)row1 * HH + k0 + 8];
    }
#pragma unroll
    for (int nt = 0; nt < 8; nt++) {
        int n = nt * 8 + g;
        float c0 = 0.f, c1 = 0.f, c2 = 0.f, c3 = 0.f;
#pragma unroll
        for (int kc = 0; kc < 4; kc++) {
            int k0 = kc * 16 + 2 * t;
            unsigned b0 = *(const unsigned*)&Wt[n * HH + k0];
            unsigned b1 = *(const unsigned*)&Wt[n * HH + k0 + 8];
            asm volatile(
                "mma.sync.aligned.m16n8k16.row.col.f32.f16.f16.f32 "
                "{%0,%1,%2,%3}, {%4,%5,%6,%7}, {%8,%9}, {%0,%1,%2,%3};\n"
                : "+f"(c0), "+f"(c1), "+f"(c2), "+f"(c3)
                : "r"(a[kc][0]), "r"(a[kc][1]), "r"(a[kc][2]), "r"(a[kc][3]),
                  "r"(b0), "r"(b1));
        }
        int col = nt * 8 + 2 * t;
        if (row0 < NROWS) *(__half2*)&Hn[(size_t)row0 * HH + col] = __floats2half2_rn(c0, c1);
        if (row1 < NROWS) *(__half2*)&Hn[(size_t)row1 * HH + col] = __floats2half2_rn(c2, c3);
    }
}

// ---------------------------------------------------------------------------
// Partial (scores+fcb) @ lin1_w. grid (2 c-tiles, RT row tiles) = 148 blocks.
// ---------------------------------------------------------------------------
__global__ void k_final(const float* __restrict__ w1, const float* __restrict__ fcb) {
    int lane = threadIdx.x;
    int ty = threadIdx.y;
    int cb = blockIdx.x * 128 + lane * 4;
    int rt = blockIdx.y;
    int n0 = rt * RPB;
    int n1 = min(NN, n0 + RPB);
    float f0 = fcb[0];

    float acc[NB][4];
#pragma unroll
    for (int b = 0; b < NB; b++)
#pragma unroll
        for (int j = 0; j < 4; j++) acc[b][j] = 0.f;

    for (int n = n0 + ty; n < n1; n += 8) {
        float4 w = __ldg((const float4*)&w1[(size_t)n * FCN + cb]);
        float sc[NB];
#pragma unroll
        for (int b = 0; b < NB; b++) sc[b] = g_scores[b * NN + n] + f0;
#pragma unroll
        for (int b = 0; b < NB; b++) {
            acc[b][0] += sc[b] * w.x;
            acc[b][1] += sc[b] * w.y;
            acc[b][2] += sc[b] * w.z;
            acc[b][3] += sc[b] * w.w;
        }
    }

    __shared__ float sh[8][32][16];
#pragma unroll
    for (int b = 0; b < NB; b++)
#pragma unroll
        for (int j = 0; j < 4; j++) sh[ty][lane][b * 4 + j] = acc[b][j];
    __syncthreads();

    int t = ty * 32 + lane;
#pragma unroll
    for (int q = t; q < 512; q += 256) {
        int ln = q >> 4, idx = q & 15;
        int b = idx >> 2, j = idx & 3;
        float s = 0.f;
#pragma unroll
        for (int k = 0; k < 8; k++) s += sh[k][ln][idx];
        g_h1part[(size_t)rt * NB * FCN + b * FCN + blockIdx.x * 128 + ln * 4 + j] = s;
    }
}

// ---------------------------------------------------------------------------
// Reduce partials, relu, lin2, log_softmax. One block, 256 threads.
// ---------------------------------------------------------------------------
__global__ void k_head(const float* __restrict__ b1v,
                       const float* __restrict__ w2, const float* __restrict__ b2v,
                       float* __restrict__ out) {
    __shared__ float h1s[NB][FCN];
    int tid = threadIdx.x;
    {
        int c = tid;
        float s[NB] = {0.f, 0.f, 0.f, 0.f};
        for (int rt = 0; rt < RT; rt++) {
            const float* p = g_h1part + (size_t)rt * NB * FCN;
#pragma unroll
            for (int b = 0; b < NB; b++) s[b] += p[b * FCN + c];
        }
        float bb = b1v[c];
#pragma unroll
        for (int b = 0; b < NB; b++) {
            float v = s[b] + bb;
            h1s[b][c] = (v > 0.f) ? v : 0.f;
        }
    }
    __syncthreads();

    int w = tid >> 5, lane = tid & 31;
    __shared__ float lg[NB][2];
    if (w < NB * 2) {
        int b = w >> 1, cls = w & 1;
        float acc = 0.f;
        for (int j = lane; j < FCN; j += 32)
            acc += h1s[b][j] * w2[j * 2 + cls];
        for (int off = 16; off; off >>= 1)
            acc += __shfl_xor_sync(0xffffffffu, acc, off);
        if (lane == 0) lg[b][cls] = acc + b2v[cls];
    }
    __syncthreads();
    if (tid < NB) {
        float l0 = lg[tid][0], l1 = lg[tid][1];
        float mm = fmaxf(l0, l1);
        float lse = mm + logf(__expf(l0 - mm) + __expf(l1 - mm));
        out[tid * 2 + 0] = l0 - lse;
        out[tid * 2 + 1] = l1 - lse;
    }
}

// ---------------------------------------------------------------------------
// Launch.  Order keeps k_agg L0 in the ncu capture slot (4th launch).
// ---------------------------------------------------------------------------
extern "C" void kernel_launch(void* const* d_in, const int* in_sizes, int n_in,
                              void* d_out, int out_size) {
    const float* x   = (const float*)d_in[0];
    const int*   ei  = (const int*)d_in[1];
    const float* W0  = (const float*)d_in[3];
    const float* as0 = (const float*)d_in[4];
    const float* ad0 = (const float*)d_in[5];
    const float* b0  = (const float*)d_in[6];
    const float* W1  = (const float*)d_in[7];
    const float* as1 = (const float*)d_in[8];
    const float* ad1 = (const float*)d_in[9];
    const float* b1  = (const float*)d_in[10];
    const float* W2  = (const float*)d_in[11];
    const float* as2 = (const float*)d_in[12];
    const float* ad2 = (const float*)d_in[13];
    const float* b2  = (const float*)d_in[14];
    const float* fcw = (const float*)d_in[15];
    const float* fcb = (const float*)d_in[16];
    const float* l1w = (const float*)d_in[17];
    const float* l1b = (const float*)d_in[18];
    const float* l2w = (const float*)d_in[19];
    const float* l2b = (const float*)d_in[20];
    float* out = (float*)d_out;

    const int* srcp = ei;
    const int* dstp = ei + NE;

    const int aggGrid = (NN * 32 + 255) / 256;
    const int gemmGrid = ((NROWS + 15) / 16 + 3) / 4;

    k_lin0<<<(NROWS + 15) / 16, 256>>>(x, W0, as0, ad0);            // 1
    k_csr<<<CSRB, 256>>>(srcp, dstp);                               // 2
    k_misc<<<1, 256>>>(W1, as1, ad1, W2, as2, ad2);                 // 3
    k_agg<false><<<aggGrid, 256>>>(/*in*/0, 0, b0, fcw);            // 4 <- profiled
    k_gemm<<<gemmGrid, 128>>>(1, 0, 0);                             // 5
    k_agg<false><<<aggGrid, 256>>>(/*in*/0, 1, b1, fcw);            // 6
    k_gemm<<<gemmGrid, 128>>>(1, 0, 1);                             // 7
    k_agg<true ><<<aggGrid, 256>>>(/*in*/0, 2, b2, fcw);            // 8
    k_final<<<dim3(2, RT), dim3(32, 8)>>>(l1w, fcb);                // 9
    k_head<<<1, 256>>>(l1b, l2w, l2b, out);                         // 10
}

// round 14
// speedup vs baseline: 1.0835x; 1.0004x over previous
#include <cuda_runtime.h>
#include <cuda_fp16.h>
#include <math.h>

#define NB   4
#define NN   15135
#define FIN0 8
#define HH   64
#define NE   302700
#define ETOT (NE + NN)
#define FCN  256
#define NL   3
#define RT   74
#define RPB  205                   // 74*205 = 15170 >= NN
#define NROWS (NB * NN)            // 60540
#define NROWS_PAD (NROWS + 16)
#define CSRB 256
#define CPB  60
#define FHB  148                   // final+head blocks
#define LOG2E 1.4426950408889634f

// ---------------------------------------------------------------------------
// Static device scratch.  h layout: [node][batch][ch] half (512 B / node).
// es/ed are PRE-SCALED by log2(e) so the edge loop uses ex2 directly.
// ---------------------------------------------------------------------------
__device__ __half g_hA16[(size_t)NROWS_PAD * HH];
__device__ __half g_hB16[(size_t)NROWS_PAD * HH];
__device__ __half g_Wt[2][HH * HH];        // W1^T, W2^T fp16 ([c][f])
__device__ float g_es4[NL][NN * NB];
__device__ float g_ed4[NL][NN * NB];
__device__ float g_scores[NB * NN];
__device__ float g_h1part[RT * NB * FCN];
__device__ float g_wa[NL][2][HH];          // pre-scaled by LOG2E
__device__ int   g_cnt[NN];                // zero-init; reset each exec
__device__ int   g_rowptr[NN + 1];
__device__ int   g_wp[NN];
__device__ int   g_srcs[ETOT];
__device__ unsigned g_bar;                 // csr barrier counter (group 256)
__device__ unsigned g_bar3;                // final/head barrier (group 148)
__device__ int   g_part[CSRB];
__device__ int   g_ppre[CSRB];

__device__ __forceinline__ __half* selbuf16(int s) { return s ? g_hB16 : g_hA16; }

__device__ __forceinline__ float ex2f(float x) {
    float r;
    asm("ex2.approx.ftz.f32 %0, %1;" : "=f"(r) : "f"(x));
    return r;
}

// Monotonic grid barriers (never reset; per-exec arrivals are multiples of
// the group size, so targets stay aligned across correctness run + replays).
__device__ __forceinline__ void gridbar256() {
    __syncthreads();
    if (threadIdx.x == 0) {
        __threadfence();
        unsigned old = atomicAdd(&g_bar, 1u);
        unsigned target = old - (old & (CSRB - 1)) + CSRB;
        volatile unsigned* p = &g_bar;
        while (*p < target) { }
        __threadfence();
    }
    __syncthreads();
}

// ---------------------------------------------------------------------------
// Fused CSR build: histogram -> scan -> scatter (validated r11/r13).
// ---------------------------------------------------------------------------
__global__ void __launch_bounds__(256) k_csr(const int* __restrict__ src,
                                             const int* __restrict__ dst) {
    int tid = threadIdx.x, bid = blockIdx.x;
    int gt = bid * 256 + tid;

    for (int i = gt; i < NE; i += CSRB * 256)
        atomicAdd(&g_cnt[dst[i]], 1);
    gridbar256();

    __shared__ int ss[64];
    int n0 = bid * CPB;
    int v = 0;
    if (tid < CPB) {
        int n = n0 + tid;
        if (n < NN) { v = g_cnt[n] + 1; g_cnt[n] = 0; }
    }
    if (tid < 64) ss[tid] = (tid < CPB) ? v : 0;
    __syncthreads();
    for (int off = 1; off < 64; off <<= 1) {
        int add = 0;
        if (tid < 64 && tid >= off) add = ss[tid - off];
        __syncthreads();
        if (tid < 64) ss[tid] += add;
        __syncthreads();
    }
    if (tid == 0) g_part[bid] = ss[63];
    gridbar256();

    if (bid == 0) {
        __shared__ int sp[CSRB];
        int pv = g_part[tid];
        sp[tid] = pv;
        __syncthreads();
        for (int off = 1; off < CSRB; off <<= 1) {
            int add = (tid >= off) ? sp[tid - off] : 0;
            __syncthreads();
            sp[tid] += add;
            __syncthreads();
        }
        g_ppre[tid] = sp[tid] - pv;
        if (tid == CSRB - 1) g_rowptr[NN] = sp[CSRB - 1];
    }
    gridbar256();

    int base = g_ppre[bid];
    if (tid < CPB) {
        int n = n0 + tid;
        if (n < NN) {
            int r = base + ss[tid] - v;
            g_rowptr[n] = r;
            g_wp[n] = r;
        }
    }
    gridbar256();

    for (int i = gt; i < ETOT; i += CSRB * 256) {
        int s, d;
        if (i < NE) { s = src[i]; d = dst[i]; }
        else        { s = d = i - NE; }
        int pos = atomicAdd(&g_wp[d], 1);
        g_srcs[pos] = s;
    }
}

// ---------------------------------------------------------------------------
// Misc prologue: wa (scaled by LOG2E) + fp16 W^T. 1 block.
// ---------------------------------------------------------------------------
__global__ void k_misc(const float* __restrict__ W1, const float* __restrict__ as1, const float* __restrict__ ad1,
                       const float* __restrict__ W2, const float* __restrict__ as2, const float* __restrict__ ad2) {
    int tid = threadIdx.x;
    if (tid < HH) {
        int f = tid;
        float s1 = 0.f, d1 = 0.f, s2 = 0.f, d2 = 0.f;
        for (int h = 0; h < HH; h++) {
            s1 += W1[f * HH + h] * as1[h]; d1 += W1[f * HH + h] * ad1[h];
            s2 += W2[f * HH + h] * as2[h]; d2 += W2[f * HH + h] * ad2[h];
        }
        g_wa[1][0][f] = s1 * LOG2E; g_wa[1][1][f] = d1 * LOG2E;
        g_wa[2][0][f] = s2 * LOG2E; g_wa[2][1][f] = d2 * LOG2E;
    }
    for (int e = tid; e < HH * HH; e += 256) {
        int c = e / HH, f = e % HH;           // Wt[c][f] = W[f][c]
        g_Wt[0][e] = __float2half(W1[f * HH + c]);
        g_Wt[1][e] = __float2half(W2[f * HH + c]);
    }
}

// ---------------------------------------------------------------------------
// Layer 0: h0 = x @ W0 (fp16), es0/ed0 (pre-scaled by LOG2E).
// ---------------------------------------------------------------------------
__global__ void k_lin0(const float* __restrict__ x, const float* __restrict__ W,
                       const float* __restrict__ as0, const float* __restrict__ ad0) {
    __shared__ float sW[FIN0 * HH];
    __shared__ float sx[16][FIN0];
    __shared__ float swa[2][FIN0];

    int tid = threadIdx.x;
    for (int i = tid; i < FIN0 * HH; i += 256) sW[i] = W[i];

    int bn0 = blockIdx.x * 16;
    for (int i = tid; i < 16 * FIN0; i += 256) {
        int bn = bn0 + i / FIN0;
        sx[i / FIN0][i % FIN0] = (bn < NROWS) ? x[(size_t)bn * FIN0 + (i % FIN0)] : 0.f;
    }
    __syncthreads();

    if (tid < 2 * FIN0) {
        int sel = tid >> 3, f = tid & 7;
        const float* a = sel ? ad0 : as0;
        float s = 0.f;
#pragma unroll
        for (int h = 0; h < HH; h++) s += sW[f * HH + h] * a[h];
        swa[sel][f] = s * LOG2E;
    }
    __syncthreads();

    int g = tid >> 6, c = tid & 63;
#pragma unroll
    for (int jj = 0; jj < 4; jj++) {
        int gg = g + jj * 4;
        int bn = bn0 + gg;
        float acc = 0.f;
#pragma unroll
        for (int f = 0; f < FIN0; f++) acc += sx[gg][f] * sW[f * HH + c];
        if (bn < NROWS) {
            int b = bn / NN, node = bn - b * NN;
            g_hA16[((size_t)node * NB + b) * HH + c] = __float2half(acc);
        }
    }

    if (tid < 32) {
        int j = tid >> 1, sel = tid & 1;
        int bn = bn0 + j;
        if (bn < NROWS) {
            float s = 0.f;
#pragma unroll
            for (int f = 0; f < FIN0; f++) s += sx[j][f] * swa[sel][f];
            int b = bn / NN, node = bn - b * NN;
            if (sel == 0) g_es4[0][node * NB + b] = s;
            else          g_ed4[0][node * NB + b] = s;
        }
    }
}

// ---------------------------------------------------------------------------
// Aggregation. One warp per node; lane = (batch, 8 channels).
// __launch_bounds__(256,7): cap regs at ~36 -> 7 blocks/SM (87.5% occ ceiling).
// ---------------------------------------------------------------------------
template <bool LAST>
__global__ void __launch_bounds__(256, 7) k_agg(int insel, int layer,
                      const float* __restrict__ bvec,
                      const float* __restrict__ fcw) {
    int tid = threadIdx.x;
    int node = (blockIdx.x * blockDim.x + tid) >> 5;
    int lane = tid & 31;
    if (node >= NN) return;

    int myb = lane >> 3;
    int mych = (lane & 7) * 8;

    const float* esl = g_es4[layer];
    int beg = g_rowptr[node], end = g_rowptr[node + 1];
    float edv = g_ed4[layer][node * NB + myb];

    const uint4* hb = (const uint4*)selbuf16(insel);
    float acc[8];
#pragma unroll
    for (int k = 0; k < 8; k++) acc[k] = 0.f;
    float den = 0.f;

#pragma unroll 4
    for (int i = beg; i < end; i++) {
        int s = __ldg(&g_srcs[i]);
        float v = __ldg(&esl[s * NB + myb]) + edv;   // pre-scaled by log2(e)
        v = fmaxf(v, 0.2f * v);                      // leaky (homogeneous)
        float ex = ex2f(v);
        den += ex;
        uint4 hv = __ldg(&hb[(size_t)s * 32 + lane]);
        float2 p0 = __half22float2(*(__half2*)&hv.x);
        float2 p1 = __half22float2(*(__half2*)&hv.y);
        float2 p2 = __half22float2(*(__half2*)&hv.z);
        float2 p3 = __half22float2(*(__half2*)&hv.w);
        acc[0] += ex * p0.x; acc[1] += ex * p0.y;
        acc[2] += ex * p1.x; acc[3] += ex * p1.y;
        acc[4] += ex * p2.x; acc[5] += ex * p2.y;
        acc[6] += ex * p3.x; acc[7] += ex * p3.y;
    }

    float inv = 1.f / den;
    float4 bb0 = __ldg((const float4*)(bvec + mych));
    float4 bb1 = __ldg((const float4*)(bvec + mych + 4));
    float o[8];
    o[0] = acc[0] * inv + bb0.x; o[1] = acc[1] * inv + bb0.y;
    o[2] = acc[2] * inv + bb0.z; o[3] = acc[3] * inv + bb0.w;
    o[4] = acc[4] * inv + bb1.x; o[5] = acc[5] * inv + bb1.y;
    o[6] = acc[6] * inv + bb1.z; o[7] = acc[7] * inv + bb1.w;
#pragma unroll
    for (int k = 0; k < 8; k++) o[k] = (o[k] > 0.f) ? o[k] : 0.f;

    // score contribution: feature index = ch*NL + layer
    {
        float sc = 0.f;
#pragma unroll
        for (int k = 0; k < 8; k++) sc += o[k] * __ldg(&fcw[(mych + k) * NL + layer]);
#pragma unroll
        for (int off = 4; off; off >>= 1)
            sc += __shfl_xor_sync(0xffffffffu, sc, off);
        if ((lane & 7) == 0) {
            if (layer == 0) g_scores[myb * NN + node] = sc;
            else            g_scores[myb * NN + node] += sc;
        }
    }

    if (!LAST) {
        int nl = layer + 1;
        float se = 0.f, sd = 0.f;
#pragma unroll
        for (int k = 0; k < 8; k++) {
            se += o[k] * g_wa[nl][0][mych + k];
            sd += o[k] * g_wa[nl][1][mych + k];
        }
#pragma unroll
        for (int off = 4; off; off >>= 1) {
            se += __shfl_xor_sync(0xffffffffu, se, off);
            sd += __shfl_xor_sync(0xffffffffu, sd, off);
        }
        if ((lane & 7) == 0) {
            g_es4[nl][node * NB + myb] = se;
            g_ed4[nl][node * NB + myb] = sd;
        }
        uint4 ov;
        ((__half2*)&ov)[0] = __floats2half2_rn(o[0], o[1]);
        ((__half2*)&ov)[1] = __floats2half2_rn(o[2], o[3]);
        ((__half2*)&ov)[2] = __floats2half2_rn(o[4], o[5]);
        ((__half2*)&ov)[3] = __floats2half2_rn(o[6], o[7]);
        ((uint4*)selbuf16(insel ^ 1))[((size_t)node * NB + myb) * 8 + (lane & 7)] = ov;
    }
}

// ---------------------------------------------------------------------------
// H_next = O @ W via mma.sync m16n8k16 (fp16 in, fp32 acc).
// ---------------------------------------------------------------------------
__global__ void __launch_bounds__(128, 1) k_gemm(int isel, int osel, int wsel) {
    const __half* O  = selbuf16(isel);
    __half* Hn = selbuf16(osel);
    const __half* Wt = g_Wt[wsel];
    int warp = (blockIdx.x * blockDim.x + threadIdx.x) >> 5;
    int lane = threadIdx.x & 31;
    int rbase = warp * 16;
    if (rbase >= NROWS) return;
    int t = lane & 3, g = lane >> 2;
    int row0 = rbase + g, row1 = row0 + 8;

    unsigned a[4][4];
#pragma unroll
    for (int kc = 0; kc < 4; kc++) {
        int k0 = kc * 16 + 2 * t;
        a[kc][0] = *(const unsigned*)&O[(size_t)row0 * HH + k0];
        a[kc][1] = *(const unsigned*)&O[(size_t)row1 * HH + k0];
        a[kc][2] = *(const unsigned*)&O[(size_t)row0 * HH + k0 + 8];
        a[kc][3] = *(const unsigned*)&O[(size_t)row1 * HH + k0 + 8];
    }
#pragma unroll
    for (int nt = 0; nt < 8; nt++) {
        int n = nt * 8 + g;
        float c0 = 0.f, c1 = 0.f, c2 = 0.f, c3 = 0.f;
#pragma unroll
        for (int kc = 0; kc < 4; kc++) {
            int k0 = kc * 16 + 2 * t;
            unsigned b0 = *(const unsigned*)&Wt[n * HH + k0];
            unsigned b1 = *(const unsigned*)&Wt[n * HH + k0 + 8];
            asm volatile(
                "mma.sync.aligned.m16n8k16.row.col.f32.f16.f16.f32 "
                "{%0,%1,%2,%3}, {%4,%5,%6,%7}, {%8,%9}, {%0,%1,%2,%3};\n"
                : "+f"(c0), "+f"(c1), "+f"(c2), "+f"(c3)
                : "r"(a[kc][0]), "r"(a[kc][1]), "r"(a[kc][2]), "r"(a[kc][3]),
                  "r"(b0), "r"(b1));
        }
        int col = nt * 8 + 2 * t;
        if (row0 < NROWS) *(__half2*)&Hn[(size_t)row0 * HH + col] = __floats2half2_rn(c0, c1);
        if (row1 < NROWS) *(__half2*)&Hn[(size_t)row1 * HH + col] = __floats2half2_rn(c2, c3);
    }
}

// ---------------------------------------------------------------------------
// FUSED final + head: 148 blocks; partial GEMM, 148-group barrier, block 0
// reduces + lin2 + log_softmax.
// ---------------------------------------------------------------------------
__global__ void __launch_bounds__(256) k_fh(const float* __restrict__ w1, const float* __restrict__ fcb,
                                            const float* __restrict__ b1v,
                                            const float* __restrict__ w2, const float* __restrict__ b2v,
                                            float* __restrict__ out) {
    int tid = threadIdx.x;
    int lane = tid & 31, ty = tid >> 5;
    int bid = blockIdx.x;
    int cbt = bid & 1, rt = bid >> 1;
    int cb = cbt * 128 + lane * 4;
    int n0 = rt * RPB;
    int n1 = min(NN, n0 + RPB);
    float f0 = __ldg(fcb);

    __shared__ float sh[8][32][16];

    float acc[NB][4];
#pragma unroll
    for (int b = 0; b < NB; b++)
#pragma unroll
        for (int j = 0; j < 4; j++) acc[b][j] = 0.f;

    for (int n = n0 + ty; n < n1; n += 8) {
        float4 w = __ldg((const float4*)&w1[(size_t)n * FCN + cb]);
        float sc[NB];
#pragma unroll
        for (int b = 0; b < NB; b++) sc[b] = g_scores[b * NN + n] + f0;
#pragma unroll
        for (int b = 0; b < NB; b++) {
            acc[b][0] += sc[b] * w.x;
            acc[b][1] += sc[b] * w.y;
            acc[b][2] += sc[b] * w.z;
            acc[b][3] += sc[b] * w.w;
        }
    }
#pragma unroll
    for (int b = 0; b < NB; b++)
#pragma unroll
        for (int j = 0; j < 4; j++) sh[ty][lane][b * 4 + j] = acc[b][j];
    __syncthreads();

#pragma unroll
    for (int q = tid; q < 512; q += 256) {
        int ln = q >> 4, idx = q & 15;
        int b = idx >> 2, j = idx & 3;
        float s = 0.f;
#pragma unroll
        for (int k = 0; k < 8; k++) s += sh[k][ln][idx];
        g_h1part[(size_t)rt * NB * FCN + b * FCN + cbt * 128 + ln * 4 + j] = s;
    }

    // 148-group monotonic barrier; only block 0 waits, others arrive & exit.
    __syncthreads();
    __shared__ unsigned s_old;
    if (tid == 0) {
        __threadfence();
        s_old = atomicAdd(&g_bar3, 1u);
    }
    __syncthreads();
    if (bid != 0) return;
    if (tid == 0) {
        unsigned old = s_old;
        unsigned target = old - (old % FHB) + FHB;
        volatile unsigned* p = &g_bar3;
        while (*p < target) { }
        __threadfence();
    }
    __syncthreads();

    // ---- head (block 0) ----
    __shared__ float h1s[NB][FCN];
    __shared__ float lg[NB][2];
    {
        int c = tid;
        float s[NB] = {0.f, 0.f, 0.f, 0.f};
        for (int r = 0; r < RT; r++) {
            const float* p = g_h1part + (size_t)r * NB * FCN;
#pragma unroll
            for (int b = 0; b < NB; b++) s[b] += p[b * FCN + c];
        }
        float bb = __ldg(&b1v[c]);
#pragma unroll
        for (int b = 0; b < NB; b++) {
            float v = s[b] + bb;
            h1s[b][c] = (v > 0.f) ? v : 0.f;
        }
    }
    __syncthreads();

    int w = tid >> 5;
    if (w < NB * 2) {
        int b = w >> 1, cls = w & 1;
        float acc2 = 0.f;
        for (int j = lane; j < FCN; j += 32)
            acc2 += h1s[b][j] * __ldg(&w2[j * 2 + cls]);
        for (int off = 16; off; off >>= 1)
            acc2 += __shfl_xor_sync(0xffffffffu, acc2, off);
        if (lane == 0) lg[b][cls] = acc2 + __ldg(&b2v[cls]);
    }
    __syncthreads();
    if (tid < NB) {
        float l0 = lg[tid][0], l1 = lg[tid][1];
        float mm = fmaxf(l0, l1);
        float lse = mm + logf(__expf(l0 - mm) + __expf(l1 - mm));
        out[tid * 2 + 0] = l0 - lse;
        out[tid * 2 + 1] = l1 - lse;
    }
}

// ---------------------------------------------------------------------------
// Launch.  Order keeps k_agg L0 in the ncu capture slot (4th launch).
// ---------------------------------------------------------------------------
extern "C" void kernel_launch(void* const* d_in, const int* in_sizes, int n_in,
                              void* d_out, int out_size) {
    const float* x   = (const float*)d_in[0];
    const int*   ei  = (const int*)d_in[1];
    const float* W0  = (const float*)d_in[3];
    const float* as0 = (const float*)d_in[4];
    const float* ad0 = (const float*)d_in[5];
    const float* b0  = (const float*)d_in[6];
    const float* W1  = (const float*)d_in[7];
    const float* as1 = (const float*)d_in[8];
    const float* ad1 = (const float*)d_in[9];
    const float* b1  = (const float*)d_in[10];
    const float* W2  = (const float*)d_in[11];
    const float* as2 = (const float*)d_in[12];
    const float* ad2 = (const float*)d_in[13];
    const float* b2  = (const float*)d_in[14];
    const float* fcw = (const float*)d_in[15];
    const float* fcb = (const float*)d_in[16];
    const float* l1w = (const float*)d_in[17];
    const float* l1b = (const float*)d_in[18];
    const float* l2w = (const float*)d_in[19];
    const float* l2b = (const float*)d_in[20];
    float* out = (float*)d_out;

    const int* srcp = ei;
    const int* dstp = ei + NE;

    const int aggGrid = (NN * 32 + 255) / 256;
    const int gemmGrid = ((NROWS + 15) / 16 + 3) / 4;

    k_lin0<<<(NROWS + 15) / 16, 256>>>(x, W0, as0, ad0);            // 1
    k_csr<<<CSRB, 256>>>(srcp, dstp);                               // 2
    k_misc<<<1, 256>>>(W1, as1, ad1, W2, as2, ad2);                 // 3
    k_agg<false><<<aggGrid, 256>>>(/*in*/0, 0, b0, fcw);            // 4 <- profiled
    k_gemm<<<gemmGrid, 128>>>(1, 0, 0);                             // 5
    k_agg<false><<<aggGrid, 256>>>(/*in*/0, 1, b1, fcw);            // 6
    k_gemm<<<gemmGrid, 128>>>(1, 0, 1);                             // 7
    k_agg<true ><<<aggGrid, 256>>>(/*in*/0, 2, b2, fcw);            // 8
    k_fh<<<FHB, 256>>>(l1w, fcb, l1b, l2w, l2b, out);               // 9
}

// round 15
// speedup vs baseline: 1.1537x; 1.0648x over previous
#include <cuda_runtime.h>
#include <cuda_fp16.h>
#include <math.h>

#define NB   4
#define NN   15135
#define FIN0 8
#define HH   64
#define NE   302700
#define ETOT (NE + NN)
#define FCN  256
#define NL   3
#define RT   74
#define RPB  205                   // 74*205 = 15170 >= NN
#define NROWS (NB * NN)            // 60540
#define NROWS_PAD (NROWS + 16)
#define CSRB 256
#define CPB  60
#define FHB  148                   // final+head blocks
#define LOG2E 1.4426950408889634f

// ---------------------------------------------------------------------------
// Static device scratch.  h layout: [node][batch][ch] half (512 B / node).
// es/ed are PRE-SCALED by log2(e) so the edge loop uses ex2 directly.
// ---------------------------------------------------------------------------
__device__ __half g_hA16[(size_t)NROWS_PAD * HH];
__device__ __half g_hB16[(size_t)NROWS_PAD * HH];
__device__ __half g_Wt[2][HH * HH];        // W1^T, W2^T fp16 ([c][f])
__device__ float g_es4[NL][NN * NB];
__device__ float g_ed4[NL][NN * NB];
__device__ float g_scores[NB * NN];
__device__ float g_h1part[RT * NB * FCN];
__device__ float g_wa[NL][2][HH];          // pre-scaled by LOG2E
__device__ int   g_cnt[NN];                // zero-init; reset each exec
__device__ int   g_rowptr[NN + 1];
__device__ int   g_wp[NN];
__device__ int   g_srcs[ETOT];
__device__ unsigned g_bar;                 // csr barrier counter (group 256)
__device__ unsigned g_bar3;                // final/head barrier (group 148)
__device__ int   g_part[CSRB];
__device__ int   g_ppre[CSRB];

__device__ __forceinline__ __half* selbuf16(int s) { return s ? g_hB16 : g_hA16; }

__device__ __forceinline__ float ex2f(float x) {
    float r;
    asm("ex2.approx.ftz.f32 %0, %1;" : "=f"(r) : "f"(x));
    return r;
}

// Monotonic grid barrier (never reset; arrivals per exec are multiples of CSRB).
__device__ __forceinline__ void gridbar256() {
    __syncthreads();
    if (threadIdx.x == 0) {
        __threadfence();
        unsigned old = atomicAdd(&g_bar, 1u);
        unsigned target = old - (old & (CSRB - 1)) + CSRB;
        volatile unsigned* p = &g_bar;
        while (*p < target) { }
        __threadfence();
    }
    __syncthreads();
}

// ---------------------------------------------------------------------------
// Fused CSR build: histogram -> scan -> scatter (validated r11/r13).
// ---------------------------------------------------------------------------
__global__ void __launch_bounds__(256) k_csr(const int* __restrict__ src,
                                             const int* __restrict__ dst) {
    int tid = threadIdx.x, bid = blockIdx.x;
    int gt = bid * 256 + tid;

    for (int i = gt; i < NE; i += CSRB * 256)
        atomicAdd(&g_cnt[dst[i]], 1);
    gridbar256();

    __shared__ int ss[64];
    int n0 = bid * CPB;
    int v = 0;
    if (tid < CPB) {
        int n = n0 + tid;
        if (n < NN) { v = g_cnt[n] + 1; g_cnt[n] = 0; }
    }
    if (tid < 64) ss[tid] = (tid < CPB) ? v : 0;
    __syncthreads();
    for (int off = 1; off < 64; off <<= 1) {
        int add = 0;
        if (tid < 64 && tid >= off) add = ss[tid - off];
        __syncthreads();
        if (tid < 64) ss[tid] += add;
        __syncthreads();
    }
    if (tid == 0) g_part[bid] = ss[63];
    gridbar256();

    if (bid == 0) {
        __shared__ int sp[CSRB];
        int pv = g_part[tid];
        sp[tid] = pv;
        __syncthreads();
        for (int off = 1; off < CSRB; off <<= 1) {
            int add = (tid >= off) ? sp[tid - off] : 0;
            __syncthreads();
            sp[tid] += add;
            __syncthreads();
        }
        g_ppre[tid] = sp[tid] - pv;
        if (tid == CSRB - 1) g_rowptr[NN] = sp[CSRB - 1];
    }
    gridbar256();

    int base = g_ppre[bid];
    if (tid < CPB) {
        int n = n0 + tid;
        if (n < NN) {
            int r = base + ss[tid] - v;
            g_rowptr[n] = r;
            g_wp[n] = r;
        }
    }
    gridbar256();

    for (int i = gt; i < ETOT; i += CSRB * 256) {
        int s, d;
        if (i < NE) { s = src[i]; d = dst[i]; }
        else        { s = d = i - NE; }
        int pos = atomicAdd(&g_wp[d], 1);
        g_srcs[pos] = s;
    }
}

// ---------------------------------------------------------------------------
// Misc prologue: wa (scaled by LOG2E) + fp16 W^T. 1 block.
// ---------------------------------------------------------------------------
__global__ void k_misc(const float* __restrict__ W1, const float* __restrict__ as1, const float* __restrict__ ad1,
                       const float* __restrict__ W2, const float* __restrict__ as2, const float* __restrict__ ad2) {
    int tid = threadIdx.x;
    if (tid < HH) {
        int f = tid;
        float s1 = 0.f, d1 = 0.f, s2 = 0.f, d2 = 0.f;
        for (int h = 0; h < HH; h++) {
            s1 += W1[f * HH + h] * as1[h]; d1 += W1[f * HH + h] * ad1[h];
            s2 += W2[f * HH + h] * as2[h]; d2 += W2[f * HH + h] * ad2[h];
        }
        g_wa[1][0][f] = s1 * LOG2E; g_wa[1][1][f] = d1 * LOG2E;
        g_wa[2][0][f] = s2 * LOG2E; g_wa[2][1][f] = d2 * LOG2E;
    }
    for (int e = tid; e < HH * HH; e += 256) {
        int c = e / HH, f = e % HH;           // Wt[c][f] = W[f][c]
        g_Wt[0][e] = __float2half(W1[f * HH + c]);
        g_Wt[1][e] = __float2half(W2[f * HH + c]);
    }
}

// ---------------------------------------------------------------------------
// Layer 0: h0 = x @ W0 (fp16), es0/ed0 (pre-scaled by LOG2E).
// ---------------------------------------------------------------------------
__global__ void k_lin0(const float* __restrict__ x, const float* __restrict__ W,
                       const float* __restrict__ as0, const float* __restrict__ ad0) {
    __shared__ float sW[FIN0 * HH];
    __shared__ float sx[16][FIN0];
    __shared__ float swa[2][FIN0];

    int tid = threadIdx.x;
    for (int i = tid; i < FIN0 * HH; i += 256) sW[i] = W[i];

    int bn0 = blockIdx.x * 16;
    for (int i = tid; i < 16 * FIN0; i += 256) {
        int bn = bn0 + i / FIN0;
        sx[i / FIN0][i % FIN0] = (bn < NROWS) ? x[(size_t)bn * FIN0 + (i % FIN0)] : 0.f;
    }
    __syncthreads();

    if (tid < 2 * FIN0) {
        int sel = tid >> 3, f = tid & 7;
        const float* a = sel ? ad0 : as0;
        float s = 0.f;
#pragma unroll
        for (int h = 0; h < HH; h++) s += sW[f * HH + h] * a[h];
        swa[sel][f] = s * LOG2E;
    }
    __syncthreads();

    int g = tid >> 6, c = tid & 63;
#pragma unroll
    for (int jj = 0; jj < 4; jj++) {
        int gg = g + jj * 4;
        int bn = bn0 + gg;
        float acc = 0.f;
#pragma unroll
        for (int f = 0; f < FIN0; f++) acc += sx[gg][f] * sW[f * HH + c];
        if (bn < NROWS) {
            int b = bn / NN, node = bn - b * NN;
            g_hA16[((size_t)node * NB + b) * HH + c] = __float2half(acc);
        }
    }

    if (tid < 32) {
        int j = tid >> 1, sel = tid & 1;
        int bn = bn0 + j;
        if (bn < NROWS) {
            float s = 0.f;
#pragma unroll
            for (int f = 0; f < FIN0; f++) s += sx[j][f] * swa[sel][f];
            int b = bn / NN, node = bn - b * NN;
            if (sel == 0) g_es4[0][node * NB + b] = s;
            else          g_ed4[0][node * NB + b] = s;
        }
    }
}

// ---------------------------------------------------------------------------
// Aggregation. One warp per node; lane = (batch, 8 channels).
// HFMA2 accumulation: ex duplicated to half2 (1 cvt) + 4 HFMA2 per edge,
// replacing 8 F2F cvt + 8 FFMA. Exponent shifted by -6 (o = acc/den is
// scale-invariant) to keep fp16 accumulators in the normal range.
// ---------------------------------------------------------------------------
template <bool LAST>
__global__ void __launch_bounds__(256, 7) k_agg(int insel, int layer,
                      const float* __restrict__ bvec,
                      const float* __restrict__ fcw) {
    int tid = threadIdx.x;
    int node = (blockIdx.x * blockDim.x + tid) >> 5;
    int lane = tid & 31;
    if (node >= NN) return;

    int myb = lane >> 3;
    int mych = (lane & 7) * 8;

    const float* esl = g_es4[layer];
    int beg = g_rowptr[node], end = g_rowptr[node + 1];
    float edv = g_ed4[layer][node * NB + myb];

    const uint4* hb = (const uint4*)selbuf16(insel);
    __half2 hz = __float2half2_rn(0.f);
    __half2 ha0 = hz, ha1 = hz, ha2 = hz, ha3 = hz;
    float den = 0.f;

#pragma unroll 4
    for (int i = beg; i < end; i++) {
        int s = __ldg(&g_srcs[i]);
        float v = __ldg(&esl[s * NB + myb]) + edv;   // pre-scaled by log2(e)
        v = fmaxf(v, 0.2f * v) - 6.0f;               // leaky + range shift
        float ex = ex2f(v);
        den += ex;
        __half2 exh = __float2half2_rn(ex);
        uint4 hv = __ldg(&hb[(size_t)s * 32 + lane]);
        ha0 = __hfma2(exh, *(__half2*)&hv.x, ha0);
        ha1 = __hfma2(exh, *(__half2*)&hv.y, ha1);
        ha2 = __hfma2(exh, *(__half2*)&hv.z, ha2);
        ha3 = __hfma2(exh, *(__half2*)&hv.w, ha3);
    }

    float inv = 1.f / den;
    float2 a0 = __half22float2(ha0);
    float2 a1 = __half22float2(ha1);
    float2 a2 = __half22float2(ha2);
    float2 a3 = __half22float2(ha3);
    float4 bb0 = __ldg((const float4*)(bvec + mych));
    float4 bb1 = __ldg((const float4*)(bvec + mych + 4));
    float o[8];
    o[0] = a0.x * inv + bb0.x; o[1] = a0.y * inv + bb0.y;
    o[2] = a1.x * inv + bb0.z; o[3] = a1.y * inv + bb0.w;
    o[4] = a2.x * inv + bb1.x; o[5] = a2.y * inv + bb1.y;
    o[6] = a3.x * inv + bb1.z; o[7] = a3.y * inv + bb1.w;
#pragma unroll
    for (int k = 0; k < 8; k++) o[k] = (o[k] > 0.f) ? o[k] : 0.f;

    // score contribution: feature index = ch*NL + layer
    {
        float sc = 0.f;
#pragma unroll
        for (int k = 0; k < 8; k++) sc += o[k] * __ldg(&fcw[(mych + k) * NL + layer]);
#pragma unroll
        for (int off = 4; off; off >>= 1)
            sc += __shfl_xor_sync(0xffffffffu, sc, off);
        if ((lane & 7) == 0) {
            if (layer == 0) g_scores[myb * NN + node] = sc;
            else            g_scores[myb * NN + node] += sc;
        }
    }

    if (!LAST) {
        int nl = layer + 1;
        float se = 0.f, sd = 0.f;
#pragma unroll
        for (int k = 0; k < 8; k++) {
            se += o[k] * g_wa[nl][0][mych + k];
            sd += o[k] * g_wa[nl][1][mych + k];
        }
#pragma unroll
        for (int off = 4; off; off >>= 1) {
            se += __shfl_xor_sync(0xffffffffu, se, off);
            sd += __shfl_xor_sync(0xffffffffu, sd, off);
        }
        if ((lane & 7) == 0) {
            g_es4[nl][node * NB + myb] = se;
            g_ed4[nl][node * NB + myb] = sd;
        }
        uint4 ov;
        ((__half2*)&ov)[0] = __floats2half2_rn(o[0], o[1]);
        ((__half2*)&ov)[1] = __floats2half2_rn(o[2], o[3]);
        ((__half2*)&ov)[2] = __floats2half2_rn(o[4], o[5]);
        ((__half2*)&ov)[3] = __floats2half2_rn(o[6], o[7]);
        ((uint4*)selbuf16(insel ^ 1))[((size_t)node * NB + myb) * 8 + (lane & 7)] = ov;
    }
}

// ---------------------------------------------------------------------------
// H_next = O @ W via mma.sync m16n8k16 (fp16 in, fp32 acc).
// ---------------------------------------------------------------------------
__global__ void __launch_bounds__(128, 1) k_gemm(int isel, int osel, int wsel) {
    const __half* O  = selbuf16(isel);
    __half* Hn = selbuf16(osel);
    const __half* Wt = g_Wt[wsel];
    int warp = (blockIdx.x * blockDim.x + threadIdx.x) >> 5;
    int lane = threadIdx.x & 31;
    int rbase = warp * 16;
    if (rbase >= NROWS) return;
    int t = lane & 3, g = lane >> 2;
    int row0 = rbase + g, row1 = row0 + 8;

    unsigned a[4][4];
#pragma unroll
    for (int kc = 0; kc < 4; kc++) {
        int k0 = kc * 16 + 2 * t;
        a[kc][0] = *(const unsigned*)&O[(size_t)row0 * HH + k0];
        a[kc][1] = *(const unsigned*)&O[(size_t)row1 * HH + k0];
        a[kc][2] = *(const unsigned*)&O[(size_t)row0 * HH + k0 + 8];
        a[kc][3] = *(const unsigned*)&O[(size_t)row1 * HH + k0 + 8];
    }
#pragma unroll
    for (int nt = 0; nt < 8; nt++) {
        int n = nt * 8 + g;
        float c0 = 0.f, c1 = 0.f, c2 = 0.f, c3 = 0.f;
#pragma unroll
        for (int kc = 0; kc < 4; kc++) {
            int k0 = kc * 16 + 2 * t;
            unsigned b0 = *(const unsigned*)&Wt[n * HH + k0];
            unsigned b1 = *(const unsigned*)&Wt[n * HH + k0 + 8];
            asm volatile(
                "mma.sync.aligned.m16n8k16.row.col.f32.f16.f16.f32 "
                "{%0,%1,%2,%3}, {%4,%5,%6,%7}, {%8,%9}, {%0,%1,%2,%3};\n"
                : "+f"(c0), "+f"(c1), "+f"(c2), "+f"(c3)
                : "r"(a[kc][0]), "r"(a[kc][1]), "r"(a[kc][2]), "r"(a[kc][3]),
                  "r"(b0), "r"(b1));
        }
        int col = nt * 8 + 2 * t;
        if (row0 < NROWS) *(__half2*)&Hn[(size_t)row0 * HH + col] = __floats2half2_rn(c0, c1);
        if (row1 < NROWS) *(__half2*)&Hn[(size_t)row1 * HH + col] = __floats2half2_rn(c2, c3);
    }
}

// ---------------------------------------------------------------------------
// FUSED final + head: 148 blocks; partial GEMM, 148-group barrier, block 0
// reduces + lin2 + log_softmax.
// ---------------------------------------------------------------------------
__global__ void __launch_bounds__(256) k_fh(const float* __restrict__ w1, const float* __restrict__ fcb,
                                            const float* __restrict__ b1v,
                                            const float* __restrict__ w2, const float* __restrict__ b2v,
                                            float* __restrict__ out) {
    int tid = threadIdx.x;
    int lane = tid & 31, ty = tid >> 5;
    int bid = blockIdx.x;
    int cbt = bid & 1, rt = bid >> 1;
    int cb = cbt * 128 + lane * 4;
    int n0 = rt * RPB;
    int n1 = min(NN, n0 + RPB);
    float f0 = __ldg(fcb);

    __shared__ float sh[8][32][16];

    float acc[NB][4];
#pragma unroll
    for (int b = 0; b < NB; b++)
#pragma unroll
        for (int j = 0; j < 4; j++) acc[b][j] = 0.f;

    for (int n = n0 + ty; n < n1; n += 8) {
        float4 w = __ldg((const float4*)&w1[(size_t)n * FCN + cb]);
        float sc[NB];
#pragma unroll
        for (int b = 0; b < NB; b++) sc[b] = g_scores[b * NN + n] + f0;
#pragma unroll
        for (int b = 0; b < NB; b++) {
            acc[b][0] += sc[b] * w.x;
            acc[b][1] += sc[b] * w.y;
            acc[b][2] += sc[b] * w.z;
            acc[b][3] += sc[b] * w.w;
        }
    }
#pragma unroll
    for (int b = 0; b < NB; b++)
#pragma unroll
        for (int j = 0; j < 4; j++) sh[ty][lane][b * 4 + j] = acc[b][j];
    __syncthreads();

#pragma unroll
    for (int q = tid; q < 512; q += 256) {
        int ln = q >> 4, idx = q & 15;
        int b = idx >> 2, j = idx & 3;
        float s = 0.f;
#pragma unroll
        for (int k = 0; k < 8; k++) s += sh[k][ln][idx];
        g_h1part[(size_t)rt * NB * FCN + b * FCN + cbt * 128 + ln * 4 + j] = s;
    }

    // 148-group monotonic barrier; only block 0 waits, others arrive & exit.
    __syncthreads();
    __shared__ unsigned s_old;
    if (tid == 0) {
        __threadfence();
        s_old = atomicAdd(&g_bar3, 1u);
    }
    __syncthreads();
    if (bid != 0) return;
    if (tid == 0) {
        unsigned old = s_old;
        unsigned target = old - (old % FHB) + FHB;
        volatile unsigned* p = &g_bar3;
        while (*p < target) { }
        __threadfence();
    }
    __syncthreads();

    // ---- head (block 0) ----
    __shared__ float h1s[NB][FCN];
    __shared__ float lg[NB][2];
    {
        int c = tid;
        float s[NB] = {0.f, 0.f, 0.f, 0.f};
        for (int r = 0; r < RT; r++) {
            const float* p = g_h1part + (size_t)r * NB * FCN;
#pragma unroll
            for (int b = 0; b < NB; b++) s[b] += p[b * FCN + c];
        }
        float bb = __ldg(&b1v[c]);
#pragma unroll
        for (int b = 0; b < NB; b++) {
            float v = s[b] + bb;
            h1s[b][c] = (v > 0.f) ? v : 0.f;
        }
    }
    __syncthreads();

    int w = tid >> 5;
    if (w < NB * 2) {
        int b = w >> 1, cls = w & 1;
        float acc2 = 0.f;
        for (int j = lane; j < FCN; j += 32)
            acc2 += h1s[b][j] * __ldg(&w2[j * 2 + cls]);
        for (int off = 16; off; off >>= 1)
            acc2 += __shfl_xor_sync(0xffffffffu, acc2, off);
        if (lane == 0) lg[b][cls] = acc2 + __ldg(&b2v[cls]);
    }
    __syncthreads();
    if (tid < NB) {
        float l0 = lg[tid][0], l1 = lg[tid][1];
        float mm = fmaxf(l0, l1);
        float lse = mm + logf(__expf(l0 - mm) + __expf(l1 - mm));
        out[tid * 2 + 0] = l0 - lse;
        out[tid * 2 + 1] = l1 - lse;
    }
}

// ---------------------------------------------------------------------------
// Launch.  Order keeps k_agg L0 in the ncu capture slot (4th launch).
// ---------------------------------------------------------------------------
extern "C" void kernel_launch(void* const* d_in, const int* in_sizes, int n_in,
                              void* d_out, int out_size) {
    const float* x   = (const float*)d_in[0];
    const int*   ei  = (const int*)d_in[1];
    const float* W0  = (const float*)d_in[3];
    const float* as0 = (const float*)d_in[4];
    const float* ad0 = (const float*)d_in[5];
    const float* b0  = (const float*)d_in[6];
    const float* W1  = (const float*)d_in[7];
    const float* as1 = (const float*)d_in[8];
    const float* ad1 = (const float*)d_in[9];
    const float* b1  = (const float*)d_in[10];
    const float* W2  = (const float*)d_in[11];
    const float* as2 = (const float*)d_in[12];
    const float* ad2 = (const float*)d_in[13];
    const float* b2  = (const float*)d_in[14];
    const float* fcw = (const float*)d_in[15];
    const float* fcb = (const float*)d_in[16];
    const float* l1w = (const float*)d_in[17];
    const float* l1b = (const float*)d_in[18];
    const float* l2w = (const float*)d_in[19];
    const float* l2b = (const float*)d_in[20];
    float* out = (float*)d_out;

    const int* srcp = ei;
    const int* dstp = ei + NE;

    const int aggGrid = (NN * 32 + 255) / 256;
    const int gemmGrid = ((NROWS + 15) / 16 + 3) / 4;

    k_lin0<<<(NROWS + 15) / 16, 256>>>(x, W0, as0, ad0);            // 1
    k_csr<<<CSRB, 256>>>(srcp, dstp);                               // 2
    k_misc<<<1, 256>>>(W1, as1, ad1, W2, as2, ad2);                 // 3
    k_agg<false><<<aggGrid, 256>>>(/*in*/0, 0, b0, fcw);            // 4 <- profiled
    k_gemm<<<gemmGrid, 128>>>(1, 0, 0);                             // 5
    k_agg<false><<<aggGrid, 256>>>(/*in*/0, 1, b1, fcw);            // 6
    k_gemm<<<gemmGrid, 128>>>(1, 0, 1);                             // 7
    k_agg<true ><<<aggGrid, 256>>>(/*in*/0, 2, b2, fcw);            // 8
    k_fh<<<FHB, 256>>>(l1w, fcb, l1b, l2w, l2b, out);               // 9
}

// round 16
// speedup vs baseline: 1.2686x; 1.0996x over previous
#include <cuda_runtime.h>
#include <cuda_fp16.h>
#include <math.h>

#define NB   4
#define NN   15135
#define FIN0 8
#define HH   64
#define NE   302700
#define ETOT (NE + NN)
#define FCN  256
#define NL   3
#define RT   74
#define RPB  205                   // 74*205 = 15170 >= NN
#define NROWS (NB * NN)            // 60540
#define NROWS_PAD (NROWS + 16)
#define CSRB 592                   // fused pre kernel blocks (4/SM)
#define CPB  26                    // nodes per block (592*26 >= NN)
#define LTILES ((NROWS + 15) / 16) // lin0 row tiles
#define FHB  148                   // final+head blocks
#define LOG2E 1.4426950408889634f

// ---------------------------------------------------------------------------
// Static device scratch.  h layout: [node][batch][ch] half (512 B / node).
// es/ed are PRE-SCALED by log2(e) so the edge loop uses ex2 directly.
// ---------------------------------------------------------------------------
__device__ __half g_hA16[(size_t)NROWS_PAD * HH];
__device__ __half g_hB16[(size_t)NROWS_PAD * HH];
__device__ __half g_Wt[2][HH * HH];        // W1^T, W2^T fp16 ([c][f])
__device__ float g_es4[NL][NN * NB];
__device__ float g_ed4[NL][NN * NB];
__device__ float g_scores[NB * NN];
__device__ float g_h1part[RT * NB * FCN];
__device__ float g_wa[NL][2][HH];          // pre-scaled by LOG2E
__device__ int   g_cnt[NN];                // zero-init; reset each exec
__device__ int   g_rowptr[NN + 1];
__device__ int   g_wp[NN];
__device__ int   g_srcs[ETOT];
__device__ unsigned g_barP;                // pre kernel barrier (group 592)
__device__ unsigned g_bar3;                // final/head barrier (group 148)
__device__ int   g_part[CSRB];
__device__ int   g_ppre[CSRB];

__device__ __forceinline__ __half* selbuf16(int s) { return s ? g_hB16 : g_hA16; }

__device__ __forceinline__ float ex2f(float x) {
    float r;
    asm("ex2.approx.ftz.f32 %0, %1;" : "=f"(r) : "f"(x));
    return r;
}

// Monotonic grid barrier (never reset; arrivals per exec are multiples of CSRB).
__device__ __forceinline__ void gridbarP() {
    __syncthreads();
    if (threadIdx.x == 0) {
        __threadfence();
        unsigned old = atomicAdd(&g_barP, 1u);
        unsigned target = old - (old % CSRB) + CSRB;
        volatile unsigned* p = &g_barP;
        while (*p < target) { }
        __threadfence();
    }
    __syncthreads();
}

// ---------------------------------------------------------------------------
// FUSED prologue: histogram atomics (fired first) + lin0 + misc overlap, then
// scan -> rowptr -> scatter. 592 blocks, monotonic grid barriers.
// ---------------------------------------------------------------------------
__global__ void __launch_bounds__(256, 7) k_pre(
    const float* __restrict__ x,  const float* __restrict__ W0,
    const float* __restrict__ as0, const float* __restrict__ ad0,
    const float* __restrict__ W1, const float* __restrict__ as1, const float* __restrict__ ad1,
    const float* __restrict__ W2, const float* __restrict__ as2, const float* __restrict__ ad2,
    const int* __restrict__ src, const int* __restrict__ dst) {

    int tid = threadIdx.x, bid = blockIdx.x;
    int gt = bid * 256 + tid;

    // ---- phase 0a: histogram (atomics drain while we compute below) ----
    for (int i = gt; i < NE; i += CSRB * 256)
        atomicAdd(&g_cnt[dst[i]], 1);

    // ---- phase 0b: misc (wa rows on blocks 0..3; Wt transpose strided) ----
    if (bid < 4 && tid < HH) {
        const float* W = (bid < 2) ? W1 : W2;
        const float* a = (bid == 0) ? as1 : (bid == 1) ? ad1 : (bid == 2) ? as2 : ad2;
        float s = 0.f;
        for (int h = 0; h < HH; h++) s += W[tid * HH + h] * a[h];
        g_wa[1 + (bid >> 1)][bid & 1][tid] = s * LOG2E;
    }
    if (gt < HH * HH) {
        int c = gt / HH, f = gt % HH;           // Wt[c][f] = W[f][c]
        g_Wt[0][gt] = __float2half(W1[f * HH + c]);
        g_Wt[1][gt] = __float2half(W2[f * HH + c]);
    }

    // ---- phase 0c: lin0 (h0 = x @ W0 fp16, es0/ed0 pre-scaled) ----
    __shared__ float sW[FIN0 * HH];
    __shared__ float sx[16][FIN0];
    __shared__ float swa[2][FIN0];
    for (int i = tid; i < FIN0 * HH; i += 256) sW[i] = W0[i];
    __syncthreads();
    if (tid < 2 * FIN0) {
        int sel = tid >> 3, f = tid & 7;
        const float* a = sel ? ad0 : as0;
        float s = 0.f;
#pragma unroll
        for (int h = 0; h < HH; h++) s += sW[f * HH + h] * a[h];
        swa[sel][f] = s * LOG2E;
    }
    __syncthreads();

    for (int tile = bid; tile < LTILES; tile += CSRB) {
        int bn0 = tile * 16;
        for (int i = tid; i < 16 * FIN0; i += 256) {
            int bn = bn0 + i / FIN0;
            sx[i / FIN0][i % FIN0] = (bn < NROWS) ? x[(size_t)bn * FIN0 + (i % FIN0)] : 0.f;
        }
        __syncthreads();

        int g = tid >> 6, c = tid & 63;
#pragma unroll
        for (int jj = 0; jj < 4; jj++) {
            int gg = g + jj * 4;
            int bn = bn0 + gg;
            float acc = 0.f;
#pragma unroll
            for (int f = 0; f < FIN0; f++) acc += sx[gg][f] * sW[f * HH + c];
            if (bn < NROWS) {
                int b = bn / NN, node = bn - b * NN;
                g_hA16[((size_t)node * NB + b) * HH + c] = __float2half(acc);
            }
        }
        if (tid < 32) {
            int j = tid >> 1, sel = tid & 1;
            int bn = bn0 + j;
            if (bn < NROWS) {
                float s = 0.f;
#pragma unroll
                for (int f = 0; f < FIN0; f++) s += sx[j][f] * swa[sel][f];
                int b = bn / NN, node = bn - b * NN;
                if (sel == 0) g_es4[0][node * NB + b] = s;
                else          g_ed4[0][node * NB + b] = s;
            }
        }
        __syncthreads();
    }
    gridbarP();

    // ---- phase B1: per-block chunk (deg+1), reset cnt, scan 26 (->32) ----
    __shared__ int ss[32];
    int n0 = bid * CPB;
    int v = 0;
    if (tid < CPB) {
        int n = n0 + tid;
        if (n < NN) { v = g_cnt[n] + 1; g_cnt[n] = 0; }
    }
    if (tid < 32) ss[tid] = (tid < CPB) ? v : 0;
    __syncthreads();
    for (int off = 1; off < 32; off <<= 1) {
        int add = 0;
        if (tid < 32 && tid >= off) add = ss[tid - off];
        __syncthreads();
        if (tid < 32) ss[tid] += add;
        __syncthreads();
    }
    if (tid == 0) g_part[bid] = ss[31];
    gridbarP();

    // ---- phase B2: block 0 scans 592 partials (3 per thread) ----
    if (bid == 0) {
        __shared__ int sp[256];
        int i0 = tid * 3;
        int a0 = (i0     < CSRB) ? g_part[i0]     : 0;
        int a1 = (i0 + 1 < CSRB) ? g_part[i0 + 1] : 0;
        int a2 = (i0 + 2 < CSRB) ? g_part[i0 + 2] : 0;
        int tsum = a0 + a1 + a2;
        sp[tid] = tsum;
        __syncthreads();
        for (int off = 1; off < 256; off <<= 1) {
            int add = (tid >= off) ? sp[tid - off] : 0;
            __syncthreads();
            sp[tid] += add;
            __syncthreads();
        }
        int pre = sp[tid] - tsum;
        if (i0     < CSRB) g_ppre[i0]     = pre;
        if (i0 + 1 < CSRB) g_ppre[i0 + 1] = pre + a0;
        if (i0 + 2 < CSRB) g_ppre[i0 + 2] = pre + a0 + a1;
        if (tid == 255) g_rowptr[NN] = sp[255];
    }
    gridbarP();

    // ---- phase B3: write rowptr / wp ----
    int base = g_ppre[bid];
    if (tid < CPB) {
        int n = n0 + tid;
        if (n < NN) {
            int r = base + ss[tid] - v;
            g_rowptr[n] = r;
            g_wp[n] = r;
        }
    }
    gridbarP();

    // ---- phase C: scatter (edges + self loops) ----
    for (int i = gt; i < ETOT; i += CSRB * 256) {
        int s, d;
        if (i < NE) { s = src[i]; d = dst[i]; }
        else        { s = d = i - NE; }
        int pos = atomicAdd(&g_wp[d], 1);
        g_srcs[pos] = s;
    }
}

// ---------------------------------------------------------------------------
// Aggregation. One warp per node; lane = (batch, 8 channels). HFMA2 accum,
// exponent shifted -6 (scale-invariant), ex2.approx, branch-free leaky.
// ---------------------------------------------------------------------------
template <bool LAST>
__global__ void __launch_bounds__(256, 7) k_agg(int insel, int layer,
                      const float* __restrict__ bvec,
                      const float* __restrict__ fcw) {
    int tid = threadIdx.x;
    int node = (blockIdx.x * blockDim.x + tid) >> 5;
    int lane = tid & 31;
    if (node >= NN) return;

    int myb = lane >> 3;
    int mych = (lane & 7) * 8;

    const float* esl = g_es4[layer];
    int beg = g_rowptr[node], end = g_rowptr[node + 1];
    float edv = g_ed4[layer][node * NB + myb];

    const uint4* hb = (const uint4*)selbuf16(insel);
    __half2 hz = __float2half2_rn(0.f);
    __half2 ha0 = hz, ha1 = hz, ha2 = hz, ha3 = hz;
    float den = 0.f;

#pragma unroll 4
    for (int i = beg; i < end; i++) {
        int s = __ldg(&g_srcs[i]);
        float v = __ldg(&esl[s * NB + myb]) + edv;   // pre-scaled by log2(e)
        v = fmaxf(v, 0.2f * v) - 6.0f;               // leaky + range shift
        float ex = ex2f(v);
        den += ex;
        __half2 exh = __float2half2_rn(ex);
        uint4 hv = __ldg(&hb[(size_t)s * 32 + lane]);
        ha0 = __hfma2(exh, *(__half2*)&hv.x, ha0);
        ha1 = __hfma2(exh, *(__half2*)&hv.y, ha1);
        ha2 = __hfma2(exh, *(__half2*)&hv.z, ha2);
        ha3 = __hfma2(exh, *(__half2*)&hv.w, ha3);
    }

    float inv = 1.f / den;
    float2 a0 = __half22float2(ha0);
    float2 a1 = __half22float2(ha1);
    float2 a2 = __half22float2(ha2);
    float2 a3 = __half22float2(ha3);
    float4 bb0 = __ldg((const float4*)(bvec + mych));
    float4 bb1 = __ldg((const float4*)(bvec + mych + 4));
    float o[8];
    o[0] = a0.x * inv + bb0.x; o[1] = a0.y * inv + bb0.y;
    o[2] = a1.x * inv + bb0.z; o[3] = a1.y * inv + bb0.w;
    o[4] = a2.x * inv + bb1.x; o[5] = a2.y * inv + bb1.y;
    o[6] = a3.x * inv + bb1.z; o[7] = a3.y * inv + bb1.w;
#pragma unroll
    for (int k = 0; k < 8; k++) o[k] = (o[k] > 0.f) ? o[k] : 0.f;

    // score contribution: feature index = ch*NL + layer
    {
        float sc = 0.f;
#pragma unroll
        for (int k = 0; k < 8; k++) sc += o[k] * __ldg(&fcw[(mych + k) * NL + layer]);
#pragma unroll
        for (int off = 4; off; off >>= 1)
            sc += __shfl_xor_sync(0xffffffffu, sc, off);
        if ((lane & 7) == 0) {
            if (layer == 0) g_scores[myb * NN + node] = sc;
            else            g_scores[myb * NN + node] += sc;
        }
    }

    if (!LAST) {
        int nl = layer + 1;
        float se = 0.f, sd = 0.f;
#pragma unroll
        for (int k = 0; k < 8; k++) {
            se += o[k] * g_wa[nl][0][mych + k];
            sd += o[k] * g_wa[nl][1][mych + k];
        }
#pragma unroll
        for (int off = 4; off; off >>= 1) {
            se += __shfl_xor_sync(0xffffffffu, se, off);
            sd += __shfl_xor_sync(0xffffffffu, sd, off);
        }
        if ((lane & 7) == 0) {
            g_es4[nl][node * NB + myb] = se;
            g_ed4[nl][node * NB + myb] = sd;
        }
        uint4 ov;
        ((__half2*)&ov)[0] = __floats2half2_rn(o[0], o[1]);
        ((__half2*)&ov)[1] = __floats2half2_rn(o[2], o[3]);
        ((__half2*)&ov)[2] = __floats2half2_rn(o[4], o[5]);
        ((__half2*)&ov)[3] = __floats2half2_rn(o[6], o[7]);
        ((uint4*)selbuf16(insel ^ 1))[((size_t)node * NB + myb) * 8 + (lane & 7)] = ov;
    }
}

// ---------------------------------------------------------------------------
// H_next = O @ W via mma.sync m16n8k16 (fp16 in, fp32 acc).
// ---------------------------------------------------------------------------
__global__ void __launch_bounds__(128, 1) k_gemm(int isel, int osel, int wsel) {
    const __half* O  = selbuf16(isel);
    __half* Hn = selbuf16(osel);
    const __half* Wt = g_Wt[wsel];
    int warp = (blockIdx.x * blockDim.x + threadIdx.x) >> 5;
    int lane = threadIdx.x & 31;
    int rbase = warp * 16;
    if (rbase >= NROWS) return;
    int t = lane & 3, g = lane >> 2;
    int row0 = rbase + g, row1 = row0 + 8;

    unsigned a[4][4];
#pragma unroll
    for (int kc = 0; kc < 4; kc++) {
        int k0 = kc * 16 + 2 * t;
        a[kc][0] = *(const unsigned*)&O[(size_t)row0 * HH + k0];
        a[kc][1] = *(const unsigned*)&O[(size_t)row1 * HH + k0];
        a[kc][2] = *(const unsigned*)&O[(size_t)row0 * HH + k0 + 8];
        a[kc][3] = *(const unsigned*)&O[(size_t)row1 * HH + k0 + 8];
    }
#pragma unroll
    for (int nt = 0; nt < 8; nt++) {
        int n = nt * 8 + g;
        float c0 = 0.f, c1 = 0.f, c2 = 0.f, c3 = 0.f;
#pragma unroll
        for (int kc = 0; kc < 4; kc++) {
            int k0 = kc * 16 + 2 * t;
            unsigned b0 = *(const unsigned*)&Wt[n * HH + k0];
            unsigned b1 = *(const unsigned*)&Wt[n * HH + k0 + 8];
            asm volatile(
                "mma.sync.aligned.m16n8k16.row.col.f32.f16.f16.f32 "
                "{%0,%1,%2,%3}, {%4,%5,%6,%7}, {%8,%9}, {%0,%1,%2,%3};\n"
                : "+f"(c0), "+f"(c1), "+f"(c2), "+f"(c3)
                : "r"(a[kc][0]), "r"(a[kc][1]), "r"(a[kc][2]), "r"(a[kc][3]),
                  "r"(b0), "r"(b1));
        }
        int col = nt * 8 + 2 * t;
        if (row0 < NROWS) *(__half2*)&Hn[(size_t)row0 * HH + col] = __floats2half2_rn(c0, c1);
        if (row1 < NROWS) *(__half2*)&Hn[(size_t)row1 * HH + col] = __floats2half2_rn(c2, c3);
    }
}

// ---------------------------------------------------------------------------
// FUSED final + head: 148 blocks; partial GEMM, 148-group barrier, block 0
// reduces + lin2 + log_softmax.
// ---------------------------------------------------------------------------
__global__ void __launch_bounds__(256) k_fh(const float* __restrict__ w1, const float* __restrict__ fcb,
                                            const float* __restrict__ b1v,
                                            const float* __restrict__ w2, const float* __restrict__ b2v,
                                            float* __restrict__ out) {
    int tid = threadIdx.x;
    int lane = tid & 31, ty = tid >> 5;
    int bid = blockIdx.x;
    int cbt = bid & 1, rt = bid >> 1;
    int cb = cbt * 128 + lane * 4;
    int n0 = rt * RPB;
    int n1 = min(NN, n0 + RPB);
    float f0 = __ldg(fcb);

    __shared__ float sh[8][32][16];

    float acc[NB][4];
#pragma unroll
    for (int b = 0; b < NB; b++)
#pragma unroll
        for (int j = 0; j < 4; j++) acc[b][j] = 0.f;

    for (int n = n0 + ty; n < n1; n += 8) {
        float4 w = __ldg((const float4*)&w1[(size_t)n * FCN + cb]);
        float sc[NB];
#pragma unroll
        for (int b = 0; b < NB; b++) sc[b] = g_scores[b * NN + n] + f0;
#pragma unroll
        for (int b = 0; b < NB; b++) {
            acc[b][0] += sc[b] * w.x;
            acc[b][1] += sc[b] * w.y;
            acc[b][2] += sc[b] * w.z;
            acc[b][3] += sc[b] * w.w;
        }
    }
#pragma unroll
    for (int b = 0; b < NB; b++)
#pragma unroll
        for (int j = 0; j < 4; j++) sh[ty][lane][b * 4 + j] = acc[b][j];
    __syncthreads();

#pragma unroll
    for (int q = tid; q < 512; q += 256) {
        int ln = q >> 4, idx = q & 15;
        int b = idx >> 2, j = idx & 3;
        float s = 0.f;
#pragma unroll
        for (int k = 0; k < 8; k++) s += sh[k][ln][idx];
        g_h1part[(size_t)rt * NB * FCN + b * FCN + cbt * 128 + ln * 4 + j] = s;
    }

    // 148-group monotonic barrier; only block 0 waits, others arrive & exit.
    __syncthreads();
    __shared__ unsigned s_old;
    if (tid == 0) {
        __threadfence();
        s_old = atomicAdd(&g_bar3, 1u);
    }
    __syncthreads();
    if (bid != 0) return;
    if (tid == 0) {
        unsigned old = s_old;
        unsigned target = old - (old % FHB) + FHB;
        volatile unsigned* p = &g_bar3;
        while (*p < target) { }
        __threadfence();
    }
    __syncthreads();

    // ---- head (block 0) ----
    __shared__ float h1s[NB][FCN];
    __shared__ float lg[NB][2];
    {
        int c = tid;
        float s[NB] = {0.f, 0.f, 0.f, 0.f};
        for (int r = 0; r < RT; r++) {
            const float* p = g_h1part + (size_t)r * NB * FCN;
#pragma unroll
            for (int b = 0; b < NB; b++) s[b] += p[b * FCN + c];
        }
        float bb = __ldg(&b1v[c]);
#pragma unroll
        for (int b = 0; b < NB; b++) {
            float v = s[b] + bb;
            h1s[b][c] = (v > 0.f) ? v : 0.f;
        }
    }
    __syncthreads();

    int w = tid >> 5;
    if (w < NB * 2) {
        int b = w >> 1, cls = w & 1;
        float acc2 = 0.f;
        for (int j = lane; j < FCN; j += 32)
            acc2 += h1s[b][j] * __ldg(&w2[j * 2 + cls]);
        for (int off = 16; off; off >>= 1)
            acc2 += __shfl_xor_sync(0xffffffffu, acc2, off);
        if (lane == 0) lg[b][cls] = acc2 + __ldg(&b2v[cls]);
    }
    __syncthreads();
    if (tid < NB) {
        float l0 = lg[tid][0], l1 = lg[tid][1];
        float mm = fmaxf(l0, l1);
        float lse = mm + logf(__expf(l0 - mm) + __expf(l1 - mm));
        out[tid * 2 + 0] = l0 - lse;
        out[tid * 2 + 1] = l1 - lse;
    }
}

// ---------------------------------------------------------------------------
// Launch: 7 kernels; #4 (agg L1) sits in the ncu capture slot.
// ---------------------------------------------------------------------------
extern "C" void kernel_launch(void* const* d_in, const int* in_sizes, int n_in,
                              void* d_out, int out_size) {
    const float* x   = (const float*)d_in[0];
    const int*   ei  = (const int*)d_in[1];
    const float* W0  = (const float*)d_in[3];
    const float* as0 = (const float*)d_in[4];
    const float* ad0 = (const float*)d_in[5];
    const float* b0  = (const float*)d_in[6];
    const float* W1  = (const float*)d_in[7];
    const float* as1 = (const float*)d_in[8];
    const float* ad1 = (const float*)d_in[9];
    const float* b1  = (const float*)d_in[10];
    const float* W2  = (const float*)d_in[11];
    const float* as2 = (const float*)d_in[12];
    const float* ad2 = (const float*)d_in[13];
    const float* b2  = (const float*)d_in[14];
    const float* fcw = (const float*)d_in[15];
    const float* fcb = (const float*)d_in[16];
    const float* l1w = (const float*)d_in[17];
    const float* l1b = (const float*)d_in[18];
    const float* l2w = (const float*)d_in[19];
    const float* l2b = (const float*)d_in[20];
    float* out = (float*)d_out;

    const int* srcp = ei;
    const int* dstp = ei + NE;

    const int aggGrid = (NN * 32 + 255) / 256;
    const int gemmGrid = ((NROWS + 15) / 16 + 3) / 4;

    k_pre<<<CSRB, 256>>>(x, W0, as0, ad0, W1, as1, ad1, W2, as2, ad2,
                         srcp, dstp);                               // 1
    k_agg<false><<<aggGrid, 256>>>(/*in*/0, 0, b0, fcw);            // 2
    k_gemm<<<gemmGrid, 128>>>(1, 0, 0);                             // 3
    k_agg<false><<<aggGrid, 256>>>(/*in*/0, 1, b1, fcw);            // 4 <- profiled
    k_gemm<<<gemmGrid, 128>>>(1, 0, 1);                             // 5
    k_agg<true ><<<aggGrid, 256>>>(/*in*/0, 2, b2, fcw);            // 6
    k_fh<<<FHB, 256>>>(l1w, fcb, l1b, l2w, l2b, out);               // 7
}